// round 1
// baseline (speedup 1.0000x reference)
#include <cuda_runtime.h>
#include <math.h>

#define SEQ    2048
#define HIDDEN 1024
#define MLP    4096
#define NH     16
#define HD     64

// ---------------- scratch (device globals: allocation-free) ----------------
__device__ float g_h  [SEQ * HIDDEN];      // ln0 output
__device__ float g_qkv[SEQ * 3 * HIDDEN];  // qkv
__device__ float g_att[SEQ * HIDDEN];      // attention output
__device__ float g_x1 [SEQ * HIDDEN];      // x + wo(att)
__device__ float g_h2 [SEQ * HIDDEN];      // ln1 output
__device__ float g_up [SEQ * MLP];         // gelu(up)

// ---------------- LayerNorm: one block (256 thr) per row --------------------
__global__ __launch_bounds__(256) void ln_kernel(
    const float* __restrict__ x, const float* __restrict__ w,
    const float* __restrict__ b, float* __restrict__ y)
{
    int row = blockIdx.x;
    int tid = threadIdx.x;
    float4 v = *(const float4*)&x[row * HIDDEN + tid * 4];
    float s  = v.x + v.y + v.z + v.w;
    float ss = v.x*v.x + v.y*v.y + v.z*v.z + v.w*v.w;
#pragma unroll
    for (int o = 16; o > 0; o >>= 1) {
        s  += __shfl_xor_sync(0xffffffffu, s,  o);
        ss += __shfl_xor_sync(0xffffffffu, ss, o);
    }
    __shared__ float2 red[8];
    int wid = tid >> 5, lane = tid & 31;
    if (lane == 0) red[wid] = make_float2(s, ss);
    __syncthreads();
    if (tid < 32) {
        float2 t = (tid < 8) ? red[tid] : make_float2(0.f, 0.f);
        s = t.x; ss = t.y;
#pragma unroll
        for (int o = 4; o > 0; o >>= 1) {
            s  += __shfl_xor_sync(0xffffffffu, s,  o);
            ss += __shfl_xor_sync(0xffffffffu, ss, o);
        }
        if (lane == 0) red[0] = make_float2(s, ss);
    }
    __syncthreads();
    float mean = red[0].x * (1.f / HIDDEN);
    float var  = red[0].y * (1.f / HIDDEN) - mean * mean;
    float rstd = rsqrtf(var + 1e-5f);
    float4 w4 = *(const float4*)&w[tid * 4];
    float4 b4 = *(const float4*)&b[tid * 4];
    float4 o4;
    o4.x = (v.x - mean) * rstd * w4.x + b4.x;
    o4.y = (v.y - mean) * rstd * w4.y + b4.y;
    o4.z = (v.z - mean) * rstd * w4.z + b4.z;
    o4.w = (v.w - mean) * rstd * w4.w + b4.w;
    *(float4*)&y[row * HIDDEN + tid * 4] = o4;
}

// ---------------- GEMM (NT): C[m,n] = sum_k A[m,k]*B[n,k] + bias -----------
// EPI: 0 = +bias, 1 = +bias+residual, 2 = +bias then tanh-GELU
__device__ __forceinline__ float gelu_tanh(float v) {
    float c = 0.7978845608028654f * (v + 0.044715f * v * v * v);
    return 0.5f * v * (1.f + tanhf(c));
}

template <int EPI>
__global__ __launch_bounds__(256) void gemm_nt(
    const float* __restrict__ A, const float* __restrict__ B,
    const float* __restrict__ bias, const float* __restrict__ res,
    float* __restrict__ C, int M, int N, int K)
{
    __shared__ float As[16][68];   // k-major, padded
    __shared__ float Bs[16][68];
    int bm = blockIdx.y * 64, bn = blockIdx.x * 64;
    int tid = threadIdx.x;
    int tr = tid >> 4, tc = tid & 15;       // 16x16 thread grid, 4x4 microtile
    int lr = tid >> 2;                      // load row 0..63
    int lc = (tid & 3) * 4;                 // load k-offset 0,4,8,12
    const float* Ap = A + (size_t)(bm + lr) * K + lc;
    const float* Bp = B + (size_t)(bn + lr) * K + lc;
    float acc[4][4] = {};
    for (int k0 = 0; k0 < K; k0 += 16) {
        float4 a4 = *(const float4*)(Ap + k0);
        float4 b4 = *(const float4*)(Bp + k0);
        As[lc + 0][lr] = a4.x; As[lc + 1][lr] = a4.y;
        As[lc + 2][lr] = a4.z; As[lc + 3][lr] = a4.w;
        Bs[lc + 0][lr] = b4.x; Bs[lc + 1][lr] = b4.y;
        Bs[lc + 2][lr] = b4.z; Bs[lc + 3][lr] = b4.w;
        __syncthreads();
#pragma unroll
        for (int kk = 0; kk < 16; kk++) {
            float4 av = *(float4*)&As[kk][tr * 4];
            float4 bv = *(float4*)&Bs[kk][tc * 4];
            float a[4] = {av.x, av.y, av.z, av.w};
            float b[4] = {bv.x, bv.y, bv.z, bv.w};
#pragma unroll
            for (int i = 0; i < 4; i++)
#pragma unroll
                for (int j = 0; j < 4; j++)
                    acc[i][j] += a[i] * b[j];
        }
        __syncthreads();
    }
    int col = bn + tc * 4;
    float4 bi = *(const float4*)&bias[col];
    float bb[4] = {bi.x, bi.y, bi.z, bi.w};
#pragma unroll
    for (int i = 0; i < 4; i++) {
        int row = bm + tr * 4 + i;
        float v[4];
#pragma unroll
        for (int j = 0; j < 4; j++) v[j] = acc[i][j] + bb[j];
        if (EPI == 1) {
            float4 r4 = *(const float4*)&res[(size_t)row * N + col];
            v[0] += r4.x; v[1] += r4.y; v[2] += r4.z; v[3] += r4.w;
        }
        if (EPI == 2) {
#pragma unroll
            for (int j = 0; j < 4; j++) v[j] = gelu_tanh(v[j]);
        }
        float4 o4 = make_float4(v[0], v[1], v[2], v[3]);
        *(float4*)&C[(size_t)row * N + col] = o4;
    }
}

// ---------------- RoPE (in-place on q,k slices of qkv) ---------------------
__global__ __launch_bounds__(256) void rope_kernel(
    float* __restrict__ qkv, const float* __restrict__ cs,
    const float* __restrict__ sn)
{
    int i = blockIdx.x * 256 + threadIdx.x;   // SEQ*2*NH*32 pairs
    int pi = i & 31;
    int h  = (i >> 5) & 15;
    int qk = (i >> 9) & 1;
    int s  = i >> 10;
    float* p = &qkv[(size_t)s * 3072 + qk * 1024 + h * 64 + pi * 2];
    float re = p[0], im = p[1];
    float cc = cs[s * 32 + pi], ssn = sn[s * 32 + pi];
    p[0] = re * cc - im * ssn;
    p[1] = re * ssn + im * cc;
}

// ---------------- Attention: flash-style, BQ=64, BK=32 ---------------------
// Segment "mask" is an ADDITIVE +1.0 bias (same segment), softmax over all keys.
__global__ __launch_bounds__(256) void attn_kernel(
    const float* __restrict__ qkv, const int* __restrict__ offs, int noffs,
    float* __restrict__ out)
{
    __shared__ float Qs[64][68];
    __shared__ float Ks[32][68];
    __shared__ float Vs[32][68];
    __shared__ float Ps[64][33];
    __shared__ int   segk[32];

    int head = blockIdx.x, qb = blockIdx.y;
    int tid = threadIdx.x;
    int r = tid >> 2;          // query row in tile (0..63)
    int c = tid & 3;           // column group (0..3): 16 dims, 8 keys

    const float scale = 0.125f;   // 1/sqrt(64), folded into Q
    int rowg = qb * 64 + r;
#pragma unroll
    for (int u = 0; u < 4; u++) {
        int col = c * 16 + u * 4;
        float4 q4 = *(const float4*)&qkv[(size_t)rowg * 3072 + head * 64 + col];
        q4.x *= scale; q4.y *= scale; q4.z *= scale; q4.w *= scale;
        *(float4*)&Qs[r][col] = q4;
    }
    int cnt = 0;
    for (int t = 0; t < noffs; t++) if (offs[t] <= rowg) cnt++;
    int segq = cnt - 1;

    float m = -1e30f, l = 0.f;
    float o[16];
#pragma unroll
    for (int dd = 0; dd < 16; dd++) o[dd] = 0.f;

    for (int kt = 0; kt < SEQ / 32; kt++) {
        __syncthreads();
        // load K,V tiles (32x64 each)
        int kr = tid >> 3;
        int kc = (tid & 7) * 8;
        int krow = kt * 32 + kr;
        const float* kp = &qkv[(size_t)krow * 3072 + 1024 + head * 64 + kc];
        const float* vp = &qkv[(size_t)krow * 3072 + 2048 + head * 64 + kc];
        *(float4*)&Ks[kr][kc]     = *(const float4*)kp;
        *(float4*)&Ks[kr][kc + 4] = *(const float4*)(kp + 4);
        *(float4*)&Vs[kr][kc]     = *(const float4*)vp;
        *(float4*)&Vs[kr][kc + 4] = *(const float4*)(vp + 4);
        if (tid < 32) {
            int kg = kt * 32 + tid;
            int c2 = 0;
            for (int t = 0; t < noffs; t++) if (offs[t] <= kg) c2++;
            segk[tid] = c2 - 1;
        }
        __syncthreads();

        // scores for 8 keys
        float s[8];
#pragma unroll
        for (int j8 = 0; j8 < 8; j8++) {
            int j = c * 8 + j8;
            float acc = (segq == segk[j]) ? 1.0f : 0.0f;
#pragma unroll
            for (int d = 0; d < 64; d += 4) {
                float4 qd = *(float4*)&Qs[r][d];
                float4 kd = *(float4*)&Ks[j][d];
                acc += qd.x * kd.x + qd.y * kd.y + qd.z * kd.z + qd.w * kd.w;
            }
            s[j8] = acc;
        }
        float mt = s[0];
#pragma unroll
        for (int j8 = 1; j8 < 8; j8++) mt = fmaxf(mt, s[j8]);
        mt = fmaxf(mt, __shfl_xor_sync(0xffffffffu, mt, 1));
        mt = fmaxf(mt, __shfl_xor_sync(0xffffffffu, mt, 2));
        float mnew = fmaxf(m, mt);
        float corr = __expf(m - mnew);
        float lp = 0.f;
#pragma unroll
        for (int j8 = 0; j8 < 8; j8++) {
            float p = __expf(s[j8] - mnew);
            Ps[r][c * 8 + j8] = p;
            lp += p;
        }
        lp += __shfl_xor_sync(0xffffffffu, lp, 1);
        lp += __shfl_xor_sync(0xffffffffu, lp, 2);
        l = l * corr + lp;
        m = mnew;
#pragma unroll
        for (int dd = 0; dd < 16; dd++) o[dd] *= corr;
        __syncwarp();
        // PV accumulate
#pragma unroll
        for (int j = 0; j < 32; j++) {
            float p = Ps[r][j];
#pragma unroll
            for (int dd = 0; dd < 16; dd += 4) {
                float4 v4 = *(float4*)&Vs[j][c * 16 + dd];
                o[dd + 0] += p * v4.x;
                o[dd + 1] += p * v4.y;
                o[dd + 2] += p * v4.z;
                o[dd + 3] += p * v4.w;
            }
        }
    }
    float inv = 1.f / l;
#pragma unroll
    for (int dd = 0; dd < 16; dd += 4) {
        float4 o4 = make_float4(o[dd] * inv, o[dd + 1] * inv,
                                o[dd + 2] * inv, o[dd + 3] * inv);
        *(float4*)&out[(size_t)rowg * HIDDEN + head * 64 + c * 16 + dd] = o4;
    }
}

// ---------------- launch ----------------------------------------------------
extern "C" void kernel_launch(void* const* d_in, const int* in_sizes, int n_in,
                              void* d_out, int out_size)
{
    const float* x        = (const float*)d_in[0];
    const float* rope_cos = (const float*)d_in[1];
    const float* rope_sin = (const float*)d_in[2];
    const float* norm0_w  = (const float*)d_in[3];
    const float* norm0_b  = (const float*)d_in[4];
    const float* norm1_w  = (const float*)d_in[5];
    const float* norm1_b  = (const float*)d_in[6];
    const float* wqkv_w   = (const float*)d_in[7];
    const float* wqkv_b   = (const float*)d_in[8];
    const float* wo_w     = (const float*)d_in[9];
    const float* wo_b     = (const float*)d_in[10];
    const float* up_w     = (const float*)d_in[11];
    const float* up_b     = (const float*)d_in[12];
    const float* down_w   = (const float*)d_in[13];
    const float* down_b   = (const float*)d_in[14];
    const int*   offs     = (const int*)d_in[15];
    int noffs = in_sizes[15];
    float* out = (float*)d_out;

    float *h, *qkv, *att, *x1, *h2, *up;
    cudaGetSymbolAddress((void**)&h,   g_h);
    cudaGetSymbolAddress((void**)&qkv, g_qkv);
    cudaGetSymbolAddress((void**)&att, g_att);
    cudaGetSymbolAddress((void**)&x1,  g_x1);
    cudaGetSymbolAddress((void**)&h2,  g_h2);
    cudaGetSymbolAddress((void**)&up,  g_up);

    // 1. LN0
    ln_kernel<<<SEQ, 256>>>(x, norm0_w, norm0_b, h);
    // 2. QKV GEMM: (2048 x 3072 x 1024)
    gemm_nt<0><<<dim3(3 * HIDDEN / 64, SEQ / 64), 256>>>(
        h, wqkv_w, wqkv_b, nullptr, qkv, SEQ, 3 * HIDDEN, HIDDEN);
    // 3. RoPE on q,k
    rope_kernel<<<(SEQ * 2 * NH * 32) / 256, 256>>>(qkv, rope_cos, rope_sin);
    // 4. attention
    attn_kernel<<<dim3(NH, SEQ / 64), 256>>>(qkv, offs, noffs, att);
    // 5. WO GEMM + residual: x1 = x + att @ wo^T + b
    gemm_nt<1><<<dim3(HIDDEN / 64, SEQ / 64), 256>>>(
        att, wo_w, wo_b, x, x1, SEQ, HIDDEN, HIDDEN);
    // 6. LN1
    ln_kernel<<<SEQ, 256>>>(x1, norm1_w, norm1_b, h2);
    // 7. UP GEMM + GELU: (2048 x 4096 x 1024)
    gemm_nt<2><<<dim3(MLP / 64, SEQ / 64), 256>>>(
        h2, up_w, up_b, nullptr, up, SEQ, MLP, HIDDEN);
    // 8. DOWN GEMM + residual: out = x1 + up @ down^T + b
    gemm_nt<1><<<dim3(HIDDEN / 64, SEQ / 64), 256>>>(
        up, down_w, down_b, x1, out, SEQ, HIDDEN, MLP);
}

// round 3
// speedup vs baseline: 1.2502x; 1.2502x over previous
#include <cuda_runtime.h>
#include <cuda_bf16.h>
#include <math.h>
#include <stdint.h>

#define SEQ    2048
#define HIDDEN 1024
#define MLP    4096
#define NH     16
#define HD     64

// ---------------- scratch (device globals: allocation-free) ----------------
__device__ __nv_bfloat16 g_h_hi [SEQ * HIDDEN];
__device__ __nv_bfloat16 g_h_lo [SEQ * HIDDEN];
__device__ float         g_qkv  [SEQ * 3 * HIDDEN];
__device__ __nv_bfloat16 g_att_hi[SEQ * HIDDEN];
__device__ __nv_bfloat16 g_att_lo[SEQ * HIDDEN];
__device__ float         g_x1  [SEQ * HIDDEN];
__device__ __nv_bfloat16 g_h2_hi[SEQ * HIDDEN];
__device__ __nv_bfloat16 g_h2_lo[SEQ * HIDDEN];
__device__ __nv_bfloat16 g_u_hi [SEQ * MLP];
__device__ __nv_bfloat16 g_u_lo [SEQ * MLP];
__device__ __nv_bfloat16 g_wqkv_hi[3 * HIDDEN * HIDDEN];
__device__ __nv_bfloat16 g_wqkv_lo[3 * HIDDEN * HIDDEN];
__device__ __nv_bfloat16 g_wo_hi [HIDDEN * HIDDEN];
__device__ __nv_bfloat16 g_wo_lo [HIDDEN * HIDDEN];
__device__ __nv_bfloat16 g_upw_hi[MLP * HIDDEN];
__device__ __nv_bfloat16 g_upw_lo[MLP * HIDDEN];
__device__ __nv_bfloat16 g_dnw_hi[HIDDEN * MLP];
__device__ __nv_bfloat16 g_dnw_lo[HIDDEN * MLP];

// ---------------- helpers ----------------------------------------------------
__device__ __forceinline__ uint32_t smem_u32(const void* p) {
    uint32_t a;
    asm("{ .reg .u64 t; cvta.to.shared.u64 t, %1; cvt.u32.u64 %0, t; }"
        : "=r"(a) : "l"(p));
    return a;
}
__device__ __forceinline__ void cp16(uint32_t saddr, const void* gptr) {
    asm volatile("cp.async.cg.shared.global [%0], [%1], 16;"
                 :: "r"(saddr), "l"(gptr));
}
__device__ __forceinline__ void cp_commit() {
    asm volatile("cp.async.commit_group;");
}
__device__ __forceinline__ void cp_wait1() {
    asm volatile("cp.async.wait_group 1;");
}
__device__ __forceinline__ void cp_wait0() {
    asm volatile("cp.async.wait_group 0;");
}
__device__ __forceinline__ void mma16816(float* c, const uint32_t* a, const uint32_t* b) {
    asm volatile(
        "mma.sync.aligned.m16n8k16.row.col.f32.bf16.bf16.f32 "
        "{%0,%1,%2,%3}, {%4,%5,%6,%7}, {%8,%9}, {%0,%1,%2,%3};"
        : "+f"(c[0]), "+f"(c[1]), "+f"(c[2]), "+f"(c[3])
        : "r"(a[0]), "r"(a[1]), "r"(a[2]), "r"(a[3]), "r"(b[0]), "r"(b[1]));
}
__device__ __forceinline__ void hilo(float v, __nv_bfloat16& h, __nv_bfloat16& l) {
    h = __float2bfloat16(v);
    l = __float2bfloat16(v - __bfloat162float(h));
}
__device__ __forceinline__ float gelu_tanh(float v) {
    float c = 0.7978845608028654f * (v + 0.044715f * v * v * v);
    return 0.5f * v * (1.f + tanhf(c));
}

// ---------------- weight conversion ------------------------------------------
__global__ __launch_bounds__(256) void conv_kernel(
    const float* __restrict__ src, __nv_bfloat16* __restrict__ hi,
    __nv_bfloat16* __restrict__ lo, int n4)
{
    int i = blockIdx.x * 256 + threadIdx.x;
    if (i >= n4) return;
    float4 v = ((const float4*)src)[i];
    __nv_bfloat16 h[4], l[4];
    hilo(v.x, h[0], l[0]); hilo(v.y, h[1], l[1]);
    hilo(v.z, h[2], l[2]); hilo(v.w, h[3], l[3]);
    *(uint2*)&hi[i * 4] = *(uint2*)h;
    *(uint2*)&lo[i * 4] = *(uint2*)l;
}

// ---------------- LayerNorm (writes bf16 hi/lo) --------------------------------
__global__ __launch_bounds__(256) void ln_kernel(
    const float* __restrict__ x, const float* __restrict__ w,
    const float* __restrict__ b, __nv_bfloat16* __restrict__ yh,
    __nv_bfloat16* __restrict__ yl)
{
    int row = blockIdx.x;
    int tid = threadIdx.x;
    float4 v = *(const float4*)&x[row * HIDDEN + tid * 4];
    float s  = v.x + v.y + v.z + v.w;
    float ss = v.x*v.x + v.y*v.y + v.z*v.z + v.w*v.w;
#pragma unroll
    for (int o = 16; o > 0; o >>= 1) {
        s  += __shfl_xor_sync(0xffffffffu, s,  o);
        ss += __shfl_xor_sync(0xffffffffu, ss, o);
    }
    __shared__ float2 red[8];
    int wid = tid >> 5, lane = tid & 31;
    if (lane == 0) red[wid] = make_float2(s, ss);
    __syncthreads();
    if (tid < 32) {
        float2 t = (tid < 8) ? red[tid] : make_float2(0.f, 0.f);
        s = t.x; ss = t.y;
#pragma unroll
        for (int o = 4; o > 0; o >>= 1) {
            s  += __shfl_xor_sync(0xffffffffu, s,  o);
            ss += __shfl_xor_sync(0xffffffffu, ss, o);
        }
        if (lane == 0) red[0] = make_float2(s, ss);
    }
    __syncthreads();
    float mean = red[0].x * (1.f / HIDDEN);
    float var  = red[0].y * (1.f / HIDDEN) - mean * mean;
    float rstd = rsqrtf(var + 1e-5f);
    float4 w4 = *(const float4*)&w[tid * 4];
    float4 b4 = *(const float4*)&b[tid * 4];
    float o0 = (v.x - mean) * rstd * w4.x + b4.x;
    float o1 = (v.y - mean) * rstd * w4.y + b4.y;
    float o2 = (v.z - mean) * rstd * w4.z + b4.z;
    float o3 = (v.w - mean) * rstd * w4.w + b4.w;
    __nv_bfloat16 h[4], l[4];
    hilo(o0, h[0], l[0]); hilo(o1, h[1], l[1]);
    hilo(o2, h[2], l[2]); hilo(o3, h[3], l[3]);
    *(uint2*)&yh[row * HIDDEN + tid * 4] = *(uint2*)h;
    *(uint2*)&yl[row * HIDDEN + tid * 4] = *(uint2*)l;
}

// ---------------- HMMA GEMM (NT): C = A @ B^T + bias -------------------------
// A[m,k], B[n,k] as bf16 hi/lo. 128x128x32 CTA tile, 8 warps of 64x32,
// mma.sync m16n8k16, hi*hi + hi*lo + lo*hi accumulation.
// EPI: 0 = +bias -> fp32; 1 = +bias+res -> fp32; 2 = +bias,GELU -> bf16 hi/lo
#define BM 128
#define BN 128
#define BK 32
#define ROWB 80                  // smem row stride in bytes (32 bf16 + pad)
#define MATB (128 * ROWB)        // 10240 bytes per matrix
#define STAGEB (4 * MATB)        // Ah, Al, Bh, Bl
#define GEMM_SMEM (2 * STAGEB)   // 81920

template <int EPI>
__global__ __launch_bounds__(256) void gemm_mma(
    const __nv_bfloat16* __restrict__ Ah, const __nv_bfloat16* __restrict__ Al,
    const __nv_bfloat16* __restrict__ Bh, const __nv_bfloat16* __restrict__ Bl,
    const float* __restrict__ bias, const float* __restrict__ res,
    float* __restrict__ C, __nv_bfloat16* __restrict__ Chi,
    __nv_bfloat16* __restrict__ Clo, int M, int N, int K)
{
    extern __shared__ char smem[];
    uint32_t sb = smem_u32(smem);
    int tid = threadIdx.x, wid = tid >> 5, lane = tid & 31;
    int bm = blockIdx.y * BM, bn = blockIdx.x * BN;
    int wm = (wid >> 2) * 64, wn = (wid & 3) * 32;
    int g = lane >> 2, t4 = lane & 3;

    float acc[4][4][4];
#pragma unroll
    for (int i = 0; i < 4; i++)
#pragma unroll
        for (int j = 0; j < 4; j++)
#pragma unroll
            for (int q = 0; q < 4; q++) acc[i][j][q] = 0.f;

    int lr0 = tid >> 2;             // 0..63
    int lc  = (tid & 3) * 8;        // half-col 0,8,16,24

    int T = K / BK;
    // prologue: stage 0
    {
        int k0 = 0;
#pragma unroll
        for (int i = 0; i < 2; i++) {
            int r = lr0 + i * 64;
            uint32_t so = sb + r * ROWB + lc * 2;
            size_t ga = (size_t)(bm + r) * K + k0 + lc;
            size_t gb = (size_t)(bn + r) * K + k0 + lc;
            cp16(so,            Ah + ga);
            cp16(so + MATB,     Al + ga);
            cp16(so + 2*MATB,   Bh + gb);
            cp16(so + 3*MATB,   Bl + gb);
        }
        cp_commit();
    }

    for (int t = 0; t < T; t++) {
        if (t + 1 < T) {
            int s = (t + 1) & 1;
            int k0 = (t + 1) * BK;
#pragma unroll
            for (int i = 0; i < 2; i++) {
                int r = lr0 + i * 64;
                uint32_t so = sb + s * STAGEB + r * ROWB + lc * 2;
                size_t ga = (size_t)(bm + r) * K + k0 + lc;
                size_t gb = (size_t)(bn + r) * K + k0 + lc;
                cp16(so,          Ah + ga);
                cp16(so + MATB,   Al + ga);
                cp16(so + 2*MATB, Bh + gb);
                cp16(so + 3*MATB, Bl + gb);
            }
            cp_commit();
            cp_wait1();
        } else {
            cp_wait0();
        }
        __syncthreads();

        char* base = smem + (t & 1) * STAGEB;
#pragma unroll
        for (int ks = 0; ks < 2; ks++) {
            int kc = ks * 16 + 2 * t4;   // half index of this thread's k pair
            uint32_t a_hi[4][4], a_lo[4][4], b_hi[4][2], b_lo[4][2];
#pragma unroll
            for (int mi = 0; mi < 4; mi++) {
                char* p = base + (wm + mi * 16 + g) * ROWB + kc * 2;
                a_hi[mi][0] = *(uint32_t*)(p);
                a_hi[mi][1] = *(uint32_t*)(p + 8 * ROWB);
                a_hi[mi][2] = *(uint32_t*)(p + 16);
                a_hi[mi][3] = *(uint32_t*)(p + 8 * ROWB + 16);
                a_lo[mi][0] = *(uint32_t*)(p + MATB);
                a_lo[mi][1] = *(uint32_t*)(p + MATB + 8 * ROWB);
                a_lo[mi][2] = *(uint32_t*)(p + MATB + 16);
                a_lo[mi][3] = *(uint32_t*)(p + MATB + 8 * ROWB + 16);
            }
#pragma unroll
            for (int ni = 0; ni < 4; ni++) {
                char* p = base + 2 * MATB + (wn + ni * 8 + g) * ROWB + kc * 2;
                b_hi[ni][0] = *(uint32_t*)(p);
                b_hi[ni][1] = *(uint32_t*)(p + 16);
                b_lo[ni][0] = *(uint32_t*)(p + MATB);
                b_lo[ni][1] = *(uint32_t*)(p + MATB + 16);
            }
#pragma unroll
            for (int mi = 0; mi < 4; mi++)
#pragma unroll
                for (int ni = 0; ni < 4; ni++) {
                    mma16816(acc[mi][ni], a_hi[mi], b_hi[ni]);
                    mma16816(acc[mi][ni], a_hi[mi], b_lo[ni]);
                    mma16816(acc[mi][ni], a_lo[mi], b_hi[ni]);
                }
        }
        __syncthreads();
    }

    // epilogue
#pragma unroll
    for (int mi = 0; mi < 4; mi++) {
#pragma unroll
        for (int ni = 0; ni < 4; ni++) {
            int n0 = bn + wn + ni * 8 + 2 * t4;
            float2 b2 = *(const float2*)&bias[n0];
            float v0 = acc[mi][ni][0] + b2.x;
            float v1 = acc[mi][ni][1] + b2.y;
            float v2 = acc[mi][ni][2] + b2.x;
            float v3 = acc[mi][ni][3] + b2.y;
            int m0 = bm + wm + mi * 16 + g;
            size_t off0 = (size_t)m0 * N + n0;
            size_t off1 = (size_t)(m0 + 8) * N + n0;
            if (EPI == 1) {
                float2 r0 = *(const float2*)&res[off0];
                float2 r1 = *(const float2*)&res[off1];
                v0 += r0.x; v1 += r0.y; v2 += r1.x; v3 += r1.y;
            }
            if (EPI == 2) {
                v0 = gelu_tanh(v0); v1 = gelu_tanh(v1);
                v2 = gelu_tanh(v2); v3 = gelu_tanh(v3);
                __nv_bfloat16 h0, l0, h1, l1, h2, l2, h3, l3;
                hilo(v0, h0, l0); hilo(v1, h1, l1);
                hilo(v2, h2, l2); hilo(v3, h3, l3);
                __nv_bfloat162 hp0 = {h0, h1}, lp0 = {l0, l1};
                __nv_bfloat162 hp1 = {h2, h3}, lp1 = {l2, l3};
                *(__nv_bfloat162*)&Chi[off0] = hp0;
                *(__nv_bfloat162*)&Clo[off0] = lp0;
                *(__nv_bfloat162*)&Chi[off1] = hp1;
                *(__nv_bfloat162*)&Clo[off1] = lp1;
            } else {
                *(float2*)&C[off0] = make_float2(v0, v1);
                *(float2*)&C[off1] = make_float2(v2, v3);
            }
        }
    }
}

// ---------------- RoPE (in-place on q,k slices of qkv, fp32) -----------------
__global__ __launch_bounds__(256) void rope_kernel(
    float* __restrict__ qkv, const float* __restrict__ cs,
    const float* __restrict__ sn)
{
    int i = blockIdx.x * 256 + threadIdx.x;
    int pi = i & 31;
    int h  = (i >> 5) & 15;
    int qk = (i >> 9) & 1;
    int s  = i >> 10;
    float* p = &qkv[(size_t)s * 3072 + qk * 1024 + h * 64 + pi * 2];
    float re = p[0], im = p[1];
    float cc = cs[s * 32 + pi], ssn = sn[s * 32 + pi];
    p[0] = re * cc - im * ssn;
    p[1] = re * ssn + im * cc;
}

// ---------------- Attention (fp32 SIMT; bf16 hi/lo out) ----------------------
__global__ __launch_bounds__(256) void attn_kernel(
    const float* __restrict__ qkv, const int* __restrict__ offs, int noffs,
    __nv_bfloat16* __restrict__ oh, __nv_bfloat16* __restrict__ ol)
{
    __shared__ float Qs[64][68];
    __shared__ float Ks[32][68];
    __shared__ float Vs[32][68];
    __shared__ float Ps[64][33];
    __shared__ int   segk[32];

    int head = blockIdx.x, qb = blockIdx.y;
    int tid = threadIdx.x;
    int r = tid >> 2;
    int c = tid & 3;

    const float scale = 0.125f;
    int rowg = qb * 64 + r;
#pragma unroll
    for (int u = 0; u < 4; u++) {
        int col = c * 16 + u * 4;
        float4 q4 = *(const float4*)&qkv[(size_t)rowg * 3072 + head * 64 + col];
        q4.x *= scale; q4.y *= scale; q4.z *= scale; q4.w *= scale;
        *(float4*)&Qs[r][col] = q4;
    }
    int cnt = 0;
    for (int t = 0; t < noffs; t++) if (offs[t] <= rowg) cnt++;
    int segq = cnt - 1;

    float m = -1e30f, l = 0.f;
    float o[16];
#pragma unroll
    for (int dd = 0; dd < 16; dd++) o[dd] = 0.f;

    for (int kt = 0; kt < SEQ / 32; kt++) {
        __syncthreads();
        int kr = tid >> 3;
        int kc = (tid & 7) * 8;
        int krow = kt * 32 + kr;
        const float* kp = &qkv[(size_t)krow * 3072 + 1024 + head * 64 + kc];
        const float* vp = &qkv[(size_t)krow * 3072 + 2048 + head * 64 + kc];
        *(float4*)&Ks[kr][kc]     = *(const float4*)kp;
        *(float4*)&Ks[kr][kc + 4] = *(const float4*)(kp + 4);
        *(float4*)&Vs[kr][kc]     = *(const float4*)vp;
        *(float4*)&Vs[kr][kc + 4] = *(const float4*)(vp + 4);
        if (tid < 32) {
            int kg = kt * 32 + tid;
            int c2 = 0;
            for (int t = 0; t < noffs; t++) if (offs[t] <= kg) c2++;
            segk[tid] = c2 - 1;
        }
        __syncthreads();

        float s[8];
#pragma unroll
        for (int j8 = 0; j8 < 8; j8++) {
            int j = c * 8 + j8;
            float acc = (segq == segk[j]) ? 1.0f : 0.0f;
#pragma unroll
            for (int d = 0; d < 64; d += 4) {
                float4 qd = *(float4*)&Qs[r][d];
                float4 kd = *(float4*)&Ks[j][d];
                acc += qd.x * kd.x + qd.y * kd.y + qd.z * kd.z + qd.w * kd.w;
            }
            s[j8] = acc;
        }
        float mt = s[0];
#pragma unroll
        for (int j8 = 1; j8 < 8; j8++) mt = fmaxf(mt, s[j8]);
        mt = fmaxf(mt, __shfl_xor_sync(0xffffffffu, mt, 1));
        mt = fmaxf(mt, __shfl_xor_sync(0xffffffffu, mt, 2));
        float mnew = fmaxf(m, mt);
        float corr = __expf(m - mnew);
        float lp = 0.f;
#pragma unroll
        for (int j8 = 0; j8 < 8; j8++) {
            float p = __expf(s[j8] - mnew);
            Ps[r][c * 8 + j8] = p;
            lp += p;
        }
        lp += __shfl_xor_sync(0xffffffffu, lp, 1);
        lp += __shfl_xor_sync(0xffffffffu, lp, 2);
        l = l * corr + lp;
        m = mnew;
#pragma unroll
        for (int dd = 0; dd < 16; dd++) o[dd] *= corr;
        __syncwarp();
#pragma unroll
        for (int j = 0; j < 32; j++) {
            float p = Ps[r][j];
#pragma unroll
            for (int dd = 0; dd < 16; dd += 4) {
                float4 v4 = *(float4*)&Vs[j][c * 16 + dd];
                o[dd + 0] += p * v4.x;
                o[dd + 1] += p * v4.y;
                o[dd + 2] += p * v4.z;
                o[dd + 3] += p * v4.w;
            }
        }
    }
    float inv = 1.f / l;
    size_t base = (size_t)rowg * HIDDEN + head * 64 + c * 16;
#pragma unroll
    for (int dd = 0; dd < 16; dd += 8) {
        __align__(16) __nv_bfloat16 h8[8], l8[8];
#pragma unroll
        for (int j = 0; j < 8; j++) hilo(o[dd + j] * inv, h8[j], l8[j]);
        *(uint4*)&oh[base + dd] = *(uint4*)h8;
        *(uint4*)&ol[base + dd] = *(uint4*)l8;
    }
}

// ---------------- launch ------------------------------------------------------
extern "C" void kernel_launch(void* const* d_in, const int* in_sizes, int n_in,
                              void* d_out, int out_size)
{
    const float* x        = (const float*)d_in[0];
    const float* rope_cos = (const float*)d_in[1];
    const float* rope_sin = (const float*)d_in[2];
    const float* norm0_w  = (const float*)d_in[3];
    const float* norm0_b  = (const float*)d_in[4];
    const float* norm1_w  = (const float*)d_in[5];
    const float* norm1_b  = (const float*)d_in[6];
    const float* wqkv_w   = (const float*)d_in[7];
    const float* wqkv_b   = (const float*)d_in[8];
    const float* wo_w     = (const float*)d_in[9];
    const float* wo_b     = (const float*)d_in[10];
    const float* up_w     = (const float*)d_in[11];
    const float* up_b     = (const float*)d_in[12];
    const float* down_w   = (const float*)d_in[13];
    const float* down_b   = (const float*)d_in[14];
    const int*   offs     = (const int*)d_in[15];
    int noffs = in_sizes[15];
    float* out = (float*)d_out;

    __nv_bfloat16 *h_hi, *h_lo, *att_hi, *att_lo, *h2_hi, *h2_lo, *u_hi, *u_lo;
    __nv_bfloat16 *wqkv_hi, *wqkv_lo, *wo_hi, *wo_lo, *upw_hi, *upw_lo, *dnw_hi, *dnw_lo;
    float *qkv, *x1;
    cudaGetSymbolAddress((void**)&h_hi, g_h_hi);
    cudaGetSymbolAddress((void**)&h_lo, g_h_lo);
    cudaGetSymbolAddress((void**)&qkv,  g_qkv);
    cudaGetSymbolAddress((void**)&att_hi, g_att_hi);
    cudaGetSymbolAddress((void**)&att_lo, g_att_lo);
    cudaGetSymbolAddress((void**)&x1,   g_x1);
    cudaGetSymbolAddress((void**)&h2_hi, g_h2_hi);
    cudaGetSymbolAddress((void**)&h2_lo, g_h2_lo);
    cudaGetSymbolAddress((void**)&u_hi, g_u_hi);
    cudaGetSymbolAddress((void**)&u_lo, g_u_lo);
    cudaGetSymbolAddress((void**)&wqkv_hi, g_wqkv_hi);
    cudaGetSymbolAddress((void**)&wqkv_lo, g_wqkv_lo);
    cudaGetSymbolAddress((void**)&wo_hi, g_wo_hi);
    cudaGetSymbolAddress((void**)&wo_lo, g_wo_lo);
    cudaGetSymbolAddress((void**)&upw_hi, g_upw_hi);
    cudaGetSymbolAddress((void**)&upw_lo, g_upw_lo);
    cudaGetSymbolAddress((void**)&dnw_hi, g_dnw_hi);
    cudaGetSymbolAddress((void**)&dnw_lo, g_dnw_lo);

    cudaFuncSetAttribute(gemm_mma<0>, cudaFuncAttributeMaxDynamicSharedMemorySize, GEMM_SMEM);
    cudaFuncSetAttribute(gemm_mma<1>, cudaFuncAttributeMaxDynamicSharedMemorySize, GEMM_SMEM);
    cudaFuncSetAttribute(gemm_mma<2>, cudaFuncAttributeMaxDynamicSharedMemorySize, GEMM_SMEM);

    // weight conversion (fp32 -> bf16 hi/lo)
    conv_kernel<<<(3*HIDDEN*HIDDEN/4 + 255)/256, 256>>>(wqkv_w, wqkv_hi, wqkv_lo, 3*HIDDEN*HIDDEN/4);
    conv_kernel<<<(HIDDEN*HIDDEN/4 + 255)/256, 256>>>(wo_w, wo_hi, wo_lo, HIDDEN*HIDDEN/4);
    conv_kernel<<<(MLP*HIDDEN/4 + 255)/256, 256>>>(up_w, upw_hi, upw_lo, MLP*HIDDEN/4);
    conv_kernel<<<(HIDDEN*MLP/4 + 255)/256, 256>>>(down_w, dnw_hi, dnw_lo, HIDDEN*MLP/4);

    // 1. LN0 -> h (bf16 hi/lo)
    ln_kernel<<<SEQ, 256>>>(x, norm0_w, norm0_b, h_hi, h_lo);
    // 2. QKV GEMM (2048 x 3072 x 1024) -> fp32 qkv
    gemm_mma<0><<<dim3(3*HIDDEN/BN, SEQ/BM), 256, GEMM_SMEM>>>(
        h_hi, h_lo, wqkv_hi, wqkv_lo, wqkv_b, nullptr,
        qkv, nullptr, nullptr, SEQ, 3*HIDDEN, HIDDEN);
    // 3. RoPE
    rope_kernel<<<(SEQ * 2 * NH * 32) / 256, 256>>>(qkv, rope_cos, rope_sin);
    // 4. attention -> att (bf16 hi/lo)
    attn_kernel<<<dim3(NH, SEQ / 64), 256>>>(qkv, offs, noffs, att_hi, att_lo);
    // 5. WO GEMM + residual -> x1 fp32
    gemm_mma<1><<<dim3(HIDDEN/BN, SEQ/BM), 256, GEMM_SMEM>>>(
        att_hi, att_lo, wo_hi, wo_lo, wo_b, x,
        x1, nullptr, nullptr, SEQ, HIDDEN, HIDDEN);
    // 6. LN1 -> h2 (bf16 hi/lo)
    ln_kernel<<<SEQ, 256>>>(x1, norm1_w, norm1_b, h2_hi, h2_lo);
    // 7. UP GEMM + GELU -> u (bf16 hi/lo)
    gemm_mma<2><<<dim3(MLP/BN, SEQ/BM), 256, GEMM_SMEM>>>(
        h2_hi, h2_lo, upw_hi, upw_lo, up_b, nullptr,
        nullptr, u_hi, u_lo, SEQ, MLP, HIDDEN);
    // 8. DOWN GEMM + residual -> out fp32
    gemm_mma<1><<<dim3(HIDDEN/BN, SEQ/BM), 256, GEMM_SMEM>>>(
        u_hi, u_lo, dnw_hi, dnw_lo, down_b, x1,
        out, nullptr, nullptr, SEQ, HIDDEN, MLP);
}

// round 4
// speedup vs baseline: 5.8685x; 4.6940x over previous
#include <cuda_runtime.h>
#include <cuda_bf16.h>
#include <math.h>
#include <stdint.h>

#define SEQ    2048
#define HIDDEN 1024
#define MLP    4096
#define NH     16
#define HD     64

// ---------------- scratch (device globals: allocation-free) ----------------
__device__ __nv_bfloat16 g_h_hi [SEQ * HIDDEN];
__device__ __nv_bfloat16 g_h_lo [SEQ * HIDDEN];
__device__ float         g_qkv  [SEQ * 3 * HIDDEN];
__device__ __nv_bfloat16 g_att_hi[SEQ * HIDDEN];
__device__ __nv_bfloat16 g_att_lo[SEQ * HIDDEN];
__device__ float         g_x1  [SEQ * HIDDEN];
__device__ __nv_bfloat16 g_h2_hi[SEQ * HIDDEN];
__device__ __nv_bfloat16 g_h2_lo[SEQ * HIDDEN];
__device__ __nv_bfloat16 g_u_hi [SEQ * MLP];
__device__ __nv_bfloat16 g_u_lo [SEQ * MLP];
__device__ __nv_bfloat16 g_wqkv_hi[3 * HIDDEN * HIDDEN];
__device__ __nv_bfloat16 g_wqkv_lo[3 * HIDDEN * HIDDEN];
__device__ __nv_bfloat16 g_wo_hi [HIDDEN * HIDDEN];
__device__ __nv_bfloat16 g_wo_lo [HIDDEN * HIDDEN];
__device__ __nv_bfloat16 g_upw_hi[MLP * HIDDEN];
__device__ __nv_bfloat16 g_upw_lo[MLP * HIDDEN];
__device__ __nv_bfloat16 g_dnw_hi[HIDDEN * MLP];
__device__ __nv_bfloat16 g_dnw_lo[HIDDEN * MLP];

// ---------------- helpers ----------------------------------------------------
__device__ __forceinline__ uint32_t smem_u32(const void* p) {
    uint32_t a;
    asm("{ .reg .u64 t; cvta.to.shared.u64 t, %1; cvt.u32.u64 %0, t; }"
        : "=r"(a) : "l"(p));
    return a;
}
__device__ __forceinline__ void cp16(uint32_t saddr, const void* gptr) {
    asm volatile("cp.async.cg.shared.global [%0], [%1], 16;"
                 :: "r"(saddr), "l"(gptr));
}
__device__ __forceinline__ void cp_commit() {
    asm volatile("cp.async.commit_group;");
}
__device__ __forceinline__ void cp_wait1() {
    asm volatile("cp.async.wait_group 1;");
}
__device__ __forceinline__ void cp_wait0() {
    asm volatile("cp.async.wait_group 0;");
}
__device__ __forceinline__ void mma16816(float* c, const uint32_t* a, const uint32_t* b) {
    asm volatile(
        "mma.sync.aligned.m16n8k16.row.col.f32.bf16.bf16.f32 "
        "{%0,%1,%2,%3}, {%4,%5,%6,%7}, {%8,%9}, {%0,%1,%2,%3};"
        : "+f"(c[0]), "+f"(c[1]), "+f"(c[2]), "+f"(c[3])
        : "r"(a[0]), "r"(a[1]), "r"(a[2]), "r"(a[3]), "r"(b[0]), "r"(b[1]));
}
__device__ __forceinline__ void ldsm2(uint32_t* r, uint32_t a) {
    asm volatile("ldmatrix.sync.aligned.m8n8.x2.shared.b16 {%0,%1}, [%2];"
                 : "=r"(r[0]), "=r"(r[1]) : "r"(a));
}
__device__ __forceinline__ void ldsm2t(uint32_t* r, uint32_t a) {
    asm volatile("ldmatrix.sync.aligned.m8n8.x2.trans.shared.b16 {%0,%1}, [%2];"
                 : "=r"(r[0]), "=r"(r[1]) : "r"(a));
}
__device__ __forceinline__ void hilo(float v, __nv_bfloat16& h, __nv_bfloat16& l) {
    h = __float2bfloat16(v);
    l = __float2bfloat16(v - __bfloat162float(h));
}
__device__ __forceinline__ uint32_t pack_hilo(float x, float y, uint32_t& lo) {
    __nv_bfloat16 hx, lx, hy, ly;
    hilo(x, hx, lx); hilo(y, hy, ly);
    __nv_bfloat162 hp = {hx, hy}, lp = {lx, ly};
    lo = *(uint32_t*)&lp;
    return *(uint32_t*)&hp;
}
__device__ __forceinline__ float gelu_tanh(float v) {
    float c = 0.7978845608028654f * (v + 0.044715f * v * v * v);
    return 0.5f * v * (1.f + tanhf(c));
}

// ---------------- weight conversion ------------------------------------------
__global__ __launch_bounds__(256) void conv_kernel(
    const float* __restrict__ src, __nv_bfloat16* __restrict__ hi,
    __nv_bfloat16* __restrict__ lo, int n4)
{
    int i = blockIdx.x * 256 + threadIdx.x;
    if (i >= n4) return;
    float4 v = ((const float4*)src)[i];
    __nv_bfloat16 h[4], l[4];
    hilo(v.x, h[0], l[0]); hilo(v.y, h[1], l[1]);
    hilo(v.z, h[2], l[2]); hilo(v.w, h[3], l[3]);
    *(uint2*)&hi[i * 4] = *(uint2*)h;
    *(uint2*)&lo[i * 4] = *(uint2*)l;
}

// ---------------- LayerNorm (writes bf16 hi/lo) --------------------------------
__global__ __launch_bounds__(256) void ln_kernel(
    const float* __restrict__ x, const float* __restrict__ w,
    const float* __restrict__ b, __nv_bfloat16* __restrict__ yh,
    __nv_bfloat16* __restrict__ yl)
{
    int row = blockIdx.x;
    int tid = threadIdx.x;
    float4 v = *(const float4*)&x[row * HIDDEN + tid * 4];
    float s  = v.x + v.y + v.z + v.w;
    float ss = v.x*v.x + v.y*v.y + v.z*v.z + v.w*v.w;
#pragma unroll
    for (int o = 16; o > 0; o >>= 1) {
        s  += __shfl_xor_sync(0xffffffffu, s,  o);
        ss += __shfl_xor_sync(0xffffffffu, ss, o);
    }
    __shared__ float2 red[8];
    int wid = tid >> 5, lane = tid & 31;
    if (lane == 0) red[wid] = make_float2(s, ss);
    __syncthreads();
    if (tid < 32) {
        float2 t = (tid < 8) ? red[tid] : make_float2(0.f, 0.f);
        s = t.x; ss = t.y;
#pragma unroll
        for (int o = 4; o > 0; o >>= 1) {
            s  += __shfl_xor_sync(0xffffffffu, s,  o);
            ss += __shfl_xor_sync(0xffffffffu, ss, o);
        }
        if (lane == 0) red[0] = make_float2(s, ss);
    }
    __syncthreads();
    float mean = red[0].x * (1.f / HIDDEN);
    float var  = red[0].y * (1.f / HIDDEN) - mean * mean;
    float rstd = rsqrtf(var + 1e-5f);
    float4 w4 = *(const float4*)&w[tid * 4];
    float4 b4 = *(const float4*)&b[tid * 4];
    float o0 = (v.x - mean) * rstd * w4.x + b4.x;
    float o1 = (v.y - mean) * rstd * w4.y + b4.y;
    float o2 = (v.z - mean) * rstd * w4.z + b4.z;
    float o3 = (v.w - mean) * rstd * w4.w + b4.w;
    __nv_bfloat16 h[4], l[4];
    hilo(o0, h[0], l[0]); hilo(o1, h[1], l[1]);
    hilo(o2, h[2], l[2]); hilo(o3, h[3], l[3]);
    *(uint2*)&yh[row * HIDDEN + tid * 4] = *(uint2*)h;
    *(uint2*)&yl[row * HIDDEN + tid * 4] = *(uint2*)l;
}

// ---------------- HMMA GEMM (NT): C = A @ B^T + bias -------------------------
#define BM 128
#define BN 128
#define BK 32
#define ROWB 80
#define MATB (128 * ROWB)
#define STAGEB (4 * MATB)
#define GEMM_SMEM (2 * STAGEB)

template <int EPI>
__global__ __launch_bounds__(256) void gemm_mma(
    const __nv_bfloat16* __restrict__ Ah, const __nv_bfloat16* __restrict__ Al,
    const __nv_bfloat16* __restrict__ Bh, const __nv_bfloat16* __restrict__ Bl,
    const float* __restrict__ bias, const float* __restrict__ res,
    float* __restrict__ C, __nv_bfloat16* __restrict__ Chi,
    __nv_bfloat16* __restrict__ Clo, int M, int N, int K)
{
    extern __shared__ char smem[];
    uint32_t sb = smem_u32(smem);
    int tid = threadIdx.x, wid = tid >> 5, lane = tid & 31;
    int bm = blockIdx.y * BM, bn = blockIdx.x * BN;
    int wm = (wid >> 2) * 64, wn = (wid & 3) * 32;
    int g = lane >> 2, t4 = lane & 3;

    float acc[4][4][4];
#pragma unroll
    for (int i = 0; i < 4; i++)
#pragma unroll
        for (int j = 0; j < 4; j++)
#pragma unroll
            for (int q = 0; q < 4; q++) acc[i][j][q] = 0.f;

    int lr0 = tid >> 2;
    int lc  = (tid & 3) * 8;

    int T = K / BK;
    {
#pragma unroll
        for (int i = 0; i < 2; i++) {
            int r = lr0 + i * 64;
            uint32_t so = sb + r * ROWB + lc * 2;
            size_t ga = (size_t)(bm + r) * K + lc;
            size_t gb = (size_t)(bn + r) * K + lc;
            cp16(so,            Ah + ga);
            cp16(so + MATB,     Al + ga);
            cp16(so + 2*MATB,   Bh + gb);
            cp16(so + 3*MATB,   Bl + gb);
        }
        cp_commit();
    }

    for (int t = 0; t < T; t++) {
        if (t + 1 < T) {
            int s = (t + 1) & 1;
            int k0 = (t + 1) * BK;
#pragma unroll
            for (int i = 0; i < 2; i++) {
                int r = lr0 + i * 64;
                uint32_t so = sb + s * STAGEB + r * ROWB + lc * 2;
                size_t ga = (size_t)(bm + r) * K + k0 + lc;
                size_t gb = (size_t)(bn + r) * K + k0 + lc;
                cp16(so,          Ah + ga);
                cp16(so + MATB,   Al + ga);
                cp16(so + 2*MATB, Bh + gb);
                cp16(so + 3*MATB, Bl + gb);
            }
            cp_commit();
            cp_wait1();
        } else {
            cp_wait0();
        }
        __syncthreads();

        char* base = smem + (t & 1) * STAGEB;
#pragma unroll
        for (int ks = 0; ks < 2; ks++) {
            int kc = ks * 16 + 2 * t4;
            uint32_t a_hi[4][4], a_lo[4][4], b_hi[4][2], b_lo[4][2];
#pragma unroll
            for (int mi = 0; mi < 4; mi++) {
                char* p = base + (wm + mi * 16 + g) * ROWB + kc * 2;
                a_hi[mi][0] = *(uint32_t*)(p);
                a_hi[mi][1] = *(uint32_t*)(p + 8 * ROWB);
                a_hi[mi][2] = *(uint32_t*)(p + 16);
                a_hi[mi][3] = *(uint32_t*)(p + 8 * ROWB + 16);
                a_lo[mi][0] = *(uint32_t*)(p + MATB);
                a_lo[mi][1] = *(uint32_t*)(p + MATB + 8 * ROWB);
                a_lo[mi][2] = *(uint32_t*)(p + MATB + 16);
                a_lo[mi][3] = *(uint32_t*)(p + MATB + 8 * ROWB + 16);
            }
#pragma unroll
            for (int ni = 0; ni < 4; ni++) {
                char* p = base + 2 * MATB + (wn + ni * 8 + g) * ROWB + kc * 2;
                b_hi[ni][0] = *(uint32_t*)(p);
                b_hi[ni][1] = *(uint32_t*)(p + 16);
                b_lo[ni][0] = *(uint32_t*)(p + MATB);
                b_lo[ni][1] = *(uint32_t*)(p + MATB + 16);
            }
#pragma unroll
            for (int mi = 0; mi < 4; mi++)
#pragma unroll
                for (int ni = 0; ni < 4; ni++) {
                    mma16816(acc[mi][ni], a_hi[mi], b_hi[ni]);
                    mma16816(acc[mi][ni], a_hi[mi], b_lo[ni]);
                    mma16816(acc[mi][ni], a_lo[mi], b_hi[ni]);
                }
        }
        __syncthreads();
    }

#pragma unroll
    for (int mi = 0; mi < 4; mi++) {
#pragma unroll
        for (int ni = 0; ni < 4; ni++) {
            int n0 = bn + wn + ni * 8 + 2 * t4;
            float2 b2 = *(const float2*)&bias[n0];
            float v0 = acc[mi][ni][0] + b2.x;
            float v1 = acc[mi][ni][1] + b2.y;
            float v2 = acc[mi][ni][2] + b2.x;
            float v3 = acc[mi][ni][3] + b2.y;
            int m0 = bm + wm + mi * 16 + g;
            size_t off0 = (size_t)m0 * N + n0;
            size_t off1 = (size_t)(m0 + 8) * N + n0;
            if (EPI == 1) {
                float2 r0 = *(const float2*)&res[off0];
                float2 r1 = *(const float2*)&res[off1];
                v0 += r0.x; v1 += r0.y; v2 += r1.x; v3 += r1.y;
            }
            if (EPI == 2) {
                v0 = gelu_tanh(v0); v1 = gelu_tanh(v1);
                v2 = gelu_tanh(v2); v3 = gelu_tanh(v3);
                uint32_t lo0, lo1;
                uint32_t hi0 = pack_hilo(v0, v1, lo0);
                uint32_t hi1 = pack_hilo(v2, v3, lo1);
                *(uint32_t*)&Chi[off0] = hi0;
                *(uint32_t*)&Clo[off0] = lo0;
                *(uint32_t*)&Chi[off1] = hi1;
                *(uint32_t*)&Clo[off1] = lo1;
            } else {
                *(float2*)&C[off0] = make_float2(v0, v1);
                *(float2*)&C[off1] = make_float2(v2, v3);
            }
        }
    }
}

// ---------------- RoPE (in-place on q,k slices of qkv, fp32) -----------------
__global__ __launch_bounds__(256) void rope_kernel(
    float* __restrict__ qkv, const float* __restrict__ cs,
    const float* __restrict__ sn)
{
    int i = blockIdx.x * 256 + threadIdx.x;
    int pi = i & 31;
    int h  = (i >> 5) & 15;
    int qk = (i >> 9) & 1;
    int s  = i >> 10;
    float* p = &qkv[(size_t)s * 3072 + qk * 1024 + h * 64 + pi * 2];
    float re = p[0], im = p[1];
    float cc = cs[s * 32 + pi], ssn = sn[s * 32 + pi];
    p[0] = re * cc - im * ssn;
    p[1] = re * ssn + im * cc;
}

// ---------------- Attention: HMMA flash, BQ=64, BKt=64 -----------------------
// Segment "mask" is an ADDITIVE +1.0 bias. Scores hi/lo-bf16 3-mma, PV same.
#define KROW 144   // 64 bf16 (128B) + 16B pad: conflict-free ldmatrix rows

__global__ __launch_bounds__(128) void attn_mma(
    const float* __restrict__ qkv, const int* __restrict__ offs, int noffs,
    __nv_bfloat16* __restrict__ oh, __nv_bfloat16* __restrict__ ol)
{
    __shared__ __align__(16) char sKh[64 * KROW];
    __shared__ __align__(16) char sKl[64 * KROW];
    __shared__ __align__(16) char sVh[64 * KROW];
    __shared__ __align__(16) char sVl[64 * KROW];
    __shared__ int segk[64];

    int head = blockIdx.x, qb = blockIdx.y;
    int tid  = threadIdx.x;
    int w = tid >> 5, lane = tid & 31;
    int g = lane >> 2, t4 = lane & 3;

    uint32_t aKh = smem_u32(sKh), aKl = smem_u32(sKl);
    uint32_t aVh = smem_u32(sVh), aVl = smem_u32(sVl);

    // ---- Q fragments (scaled by 1/8, hi/lo split), kept in registers ----
    uint32_t qh[4][4], ql[4][4];
    int qr0 = qb * 64 + w * 16 + g;
    {
        const float* q0 = qkv + (size_t)qr0 * 3072 + head * 64;
        const float* q8 = q0 + 8 * 3072;
#pragma unroll
        for (int kk = 0; kk < 4; kk++) {
            int c0 = kk * 16 + 2 * t4;
            float2 v00 = *(const float2*)(q0 + c0);
            float2 v10 = *(const float2*)(q8 + c0);
            float2 v01 = *(const float2*)(q0 + c0 + 8);
            float2 v11 = *(const float2*)(q8 + c0 + 8);
            qh[kk][0] = pack_hilo(v00.x * 0.125f, v00.y * 0.125f, ql[kk][0]);
            qh[kk][1] = pack_hilo(v10.x * 0.125f, v10.y * 0.125f, ql[kk][1]);
            qh[kk][2] = pack_hilo(v01.x * 0.125f, v01.y * 0.125f, ql[kk][2]);
            qh[kk][3] = pack_hilo(v11.x * 0.125f, v11.y * 0.125f, ql[kk][3]);
        }
    }
    int segq0 = 0, segq8 = 0;
    for (int t = 0; t < noffs; t++) {
        if (offs[t] <= qr0)     segq0++;
        if (offs[t] <= qr0 + 8) segq8++;
    }
    segq0--; segq8--;

    float o[8][4];
#pragma unroll
    for (int nt = 0; nt < 8; nt++)
#pragma unroll
        for (int q = 0; q < 4; q++) o[nt][q] = 0.f;
    float m0 = -1e30f, m8 = -1e30f, l0 = 0.f, l8 = 0.f;

    for (int kt = 0; kt < SEQ / 64; kt++) {
        __syncthreads();
        // cooperative K/V tile load: fp32 -> bf16 hi/lo, row-major [key][dim]
#pragma unroll
        for (int i = 0; i < 8; i++) {
            int fid = tid + i * 128;
            int row = fid >> 4;
            int c4  = (fid & 15) * 4;
            const float* kp = qkv + (size_t)(kt * 64 + row) * 3072 + 1024 + head * 64 + c4;
            float4 kv = *(const float4*)kp;
            float4 vv = *(const float4*)(kp + 1024);
            __nv_bfloat16 khh[4], kll[4], vhh[4], vll[4];
            hilo(kv.x, khh[0], kll[0]); hilo(kv.y, khh[1], kll[1]);
            hilo(kv.z, khh[2], kll[2]); hilo(kv.w, khh[3], kll[3]);
            hilo(vv.x, vhh[0], vll[0]); hilo(vv.y, vhh[1], vll[1]);
            hilo(vv.z, vhh[2], vll[2]); hilo(vv.w, vhh[3], vll[3]);
            int so = row * KROW + c4 * 2;
            *(uint2*)(sKh + so) = *(uint2*)khh;
            *(uint2*)(sKl + so) = *(uint2*)kll;
            *(uint2*)(sVh + so) = *(uint2*)vhh;
            *(uint2*)(sVl + so) = *(uint2*)vll;
        }
        if (tid < 64) {
            int kg = kt * 64 + tid;
            int c2 = 0;
            for (int t = 0; t < noffs; t++) if (offs[t] <= kg) c2++;
            segk[tid] = c2 - 1;
        }
        __syncthreads();

        // ---- scores S = Q @ K^T (3-mma hi/lo) ----
        float s[8][4];
#pragma unroll
        for (int nt = 0; nt < 8; nt++)
#pragma unroll
            for (int q = 0; q < 4; q++) s[nt][q] = 0.f;
#pragma unroll
        for (int kk = 0; kk < 4; kk++) {
#pragma unroll
            for (int nt = 0; nt < 8; nt++) {
                uint32_t off = (uint32_t)((nt * 8 + (lane & 7)) * KROW +
                                          (kk * 16 + ((lane >> 3) & 1) * 8) * 2);
                uint32_t bh[2], bl[2];
                ldsm2(bh, aKh + off);
                ldsm2(bl, aKl + off);
                mma16816(s[nt], qh[kk], bh);
                mma16816(s[nt], qh[kk], bl);
                mma16816(s[nt], ql[kk], bh);
            }
        }
        // ---- +1.0 segment bias, online softmax ----
        float mt0 = -1e30f, mt8 = -1e30f;
#pragma unroll
        for (int nt = 0; nt < 8; nt++) {
            int sc0 = segk[nt * 8 + 2 * t4];
            int sc1 = segk[nt * 8 + 2 * t4 + 1];
            s[nt][0] += (segq0 == sc0) ? 1.f : 0.f;
            s[nt][1] += (segq0 == sc1) ? 1.f : 0.f;
            s[nt][2] += (segq8 == sc0) ? 1.f : 0.f;
            s[nt][3] += (segq8 == sc1) ? 1.f : 0.f;
            mt0 = fmaxf(mt0, fmaxf(s[nt][0], s[nt][1]));
            mt8 = fmaxf(mt8, fmaxf(s[nt][2], s[nt][3]));
        }
        mt0 = fmaxf(mt0, __shfl_xor_sync(0xffffffffu, mt0, 1));
        mt0 = fmaxf(mt0, __shfl_xor_sync(0xffffffffu, mt0, 2));
        mt8 = fmaxf(mt8, __shfl_xor_sync(0xffffffffu, mt8, 1));
        mt8 = fmaxf(mt8, __shfl_xor_sync(0xffffffffu, mt8, 2));
        float mn0 = fmaxf(m0, mt0), mn8 = fmaxf(m8, mt8);
        float corr0 = __expf(m0 - mn0), corr8 = __expf(m8 - mn8);
        m0 = mn0; m8 = mn8;
        float lp0 = 0.f, lp8 = 0.f;
#pragma unroll
        for (int nt = 0; nt < 8; nt++) {
            s[nt][0] = __expf(s[nt][0] - mn0);
            s[nt][1] = __expf(s[nt][1] - mn0);
            s[nt][2] = __expf(s[nt][2] - mn8);
            s[nt][3] = __expf(s[nt][3] - mn8);
            lp0 += s[nt][0] + s[nt][1];
            lp8 += s[nt][2] + s[nt][3];
        }
        lp0 += __shfl_xor_sync(0xffffffffu, lp0, 1);
        lp0 += __shfl_xor_sync(0xffffffffu, lp0, 2);
        lp8 += __shfl_xor_sync(0xffffffffu, lp8, 1);
        lp8 += __shfl_xor_sync(0xffffffffu, lp8, 2);
        l0 = l0 * corr0 + lp0;
        l8 = l8 * corr8 + lp8;
#pragma unroll
        for (int nt = 0; nt < 8; nt++) {
            o[nt][0] *= corr0; o[nt][1] *= corr0;
            o[nt][2] *= corr8; o[nt][3] *= corr8;
        }
        // ---- O += P @ V (P frags built in-register from S frags) ----
#pragma unroll
        for (int kk = 0; kk < 4; kk++) {
            uint32_t pah[4], pal[4];
            pah[0] = pack_hilo(s[2*kk][0],   s[2*kk][1],   pal[0]);
            pah[1] = pack_hilo(s[2*kk][2],   s[2*kk][3],   pal[1]);
            pah[2] = pack_hilo(s[2*kk+1][0], s[2*kk+1][1], pal[2]);
            pah[3] = pack_hilo(s[2*kk+1][2], s[2*kk+1][3], pal[3]);
#pragma unroll
            for (int nt = 0; nt < 8; nt++) {
                uint32_t off = (uint32_t)((kk * 16 + (lane & 15)) * KROW + nt * 16);
                uint32_t vh[2], vl[2];
                ldsm2t(vh, aVh + off);
                ldsm2t(vl, aVl + off);
                mma16816(o[nt], pah, vh);
                mma16816(o[nt], pah, vl);
                mma16816(o[nt], pal, vh);
            }
        }
    }

    // ---- finalize: O / l, write bf16 hi/lo ----
    float inv0 = 1.f / l0, inv8 = 1.f / l8;
    size_t r0off = (size_t)qr0 * HIDDEN + head * 64;
    size_t r8off = r0off + 8 * HIDDEN;
#pragma unroll
    for (int nt = 0; nt < 8; nt++) {
        int col = nt * 8 + 2 * t4;
        uint32_t lo0, lo1;
        uint32_t hi0 = pack_hilo(o[nt][0] * inv0, o[nt][1] * inv0, lo0);
        uint32_t hi1 = pack_hilo(o[nt][2] * inv8, o[nt][3] * inv8, lo1);
        *(uint32_t*)&oh[r0off + col] = hi0;
        *(uint32_t*)&ol[r0off + col] = lo0;
        *(uint32_t*)&oh[r8off + col] = hi1;
        *(uint32_t*)&ol[r8off + col] = lo1;
    }
}

// ---------------- launch ------------------------------------------------------
extern "C" void kernel_launch(void* const* d_in, const int* in_sizes, int n_in,
                              void* d_out, int out_size)
{
    const float* x        = (const float*)d_in[0];
    const float* rope_cos = (const float*)d_in[1];
    const float* rope_sin = (const float*)d_in[2];
    const float* norm0_w  = (const float*)d_in[3];
    const float* norm0_b  = (const float*)d_in[4];
    const float* norm1_w  = (const float*)d_in[5];
    const float* norm1_b  = (const float*)d_in[6];
    const float* wqkv_w   = (const float*)d_in[7];
    const float* wqkv_b   = (const float*)d_in[8];
    const float* wo_w     = (const float*)d_in[9];
    const float* wo_b     = (const float*)d_in[10];
    const float* up_w     = (const float*)d_in[11];
    const float* up_b     = (const float*)d_in[12];
    const float* down_w   = (const float*)d_in[13];
    const float* down_b   = (const float*)d_in[14];
    const int*   offs     = (const int*)d_in[15];
    int noffs = in_sizes[15];
    float* out = (float*)d_out;

    __nv_bfloat16 *h_hi, *h_lo, *att_hi, *att_lo, *h2_hi, *h2_lo, *u_hi, *u_lo;
    __nv_bfloat16 *wqkv_hi, *wqkv_lo, *wo_hi, *wo_lo, *upw_hi, *upw_lo, *dnw_hi, *dnw_lo;
    float *qkv, *x1;
    cudaGetSymbolAddress((void**)&h_hi, g_h_hi);
    cudaGetSymbolAddress((void**)&h_lo, g_h_lo);
    cudaGetSymbolAddress((void**)&qkv,  g_qkv);
    cudaGetSymbolAddress((void**)&att_hi, g_att_hi);
    cudaGetSymbolAddress((void**)&att_lo, g_att_lo);
    cudaGetSymbolAddress((void**)&x1,   g_x1);
    cudaGetSymbolAddress((void**)&h2_hi, g_h2_hi);
    cudaGetSymbolAddress((void**)&h2_lo, g_h2_lo);
    cudaGetSymbolAddress((void**)&u_hi, g_u_hi);
    cudaGetSymbolAddress((void**)&u_lo, g_u_lo);
    cudaGetSymbolAddress((void**)&wqkv_hi, g_wqkv_hi);
    cudaGetSymbolAddress((void**)&wqkv_lo, g_wqkv_lo);
    cudaGetSymbolAddress((void**)&wo_hi, g_wo_hi);
    cudaGetSymbolAddress((void**)&wo_lo, g_wo_lo);
    cudaGetSymbolAddress((void**)&upw_hi, g_upw_hi);
    cudaGetSymbolAddress((void**)&upw_lo, g_upw_lo);
    cudaGetSymbolAddress((void**)&dnw_hi, g_dnw_hi);
    cudaGetSymbolAddress((void**)&dnw_lo, g_dnw_lo);

    cudaFuncSetAttribute(gemm_mma<0>, cudaFuncAttributeMaxDynamicSharedMemorySize, GEMM_SMEM);
    cudaFuncSetAttribute(gemm_mma<1>, cudaFuncAttributeMaxDynamicSharedMemorySize, GEMM_SMEM);
    cudaFuncSetAttribute(gemm_mma<2>, cudaFuncAttributeMaxDynamicSharedMemorySize, GEMM_SMEM);

    conv_kernel<<<(3*HIDDEN*HIDDEN/4 + 255)/256, 256>>>(wqkv_w, wqkv_hi, wqkv_lo, 3*HIDDEN*HIDDEN/4);
    conv_kernel<<<(HIDDEN*HIDDEN/4 + 255)/256, 256>>>(wo_w, wo_hi, wo_lo, HIDDEN*HIDDEN/4);
    conv_kernel<<<(MLP*HIDDEN/4 + 255)/256, 256>>>(up_w, upw_hi, upw_lo, MLP*HIDDEN/4);
    conv_kernel<<<(HIDDEN*MLP/4 + 255)/256, 256>>>(down_w, dnw_hi, dnw_lo, HIDDEN*MLP/4);

    // 1. LN0 -> h (bf16 hi/lo)
    ln_kernel<<<SEQ, 256>>>(x, norm0_w, norm0_b, h_hi, h_lo);
    // 2. QKV GEMM -> fp32 qkv
    gemm_mma<0><<<dim3(3*HIDDEN/BN, SEQ/BM), 256, GEMM_SMEM>>>(
        h_hi, h_lo, wqkv_hi, wqkv_lo, wqkv_b, nullptr,
        qkv, nullptr, nullptr, SEQ, 3*HIDDEN, HIDDEN);
    // 3. RoPE
    rope_kernel<<<(SEQ * 2 * NH * 32) / 256, 256>>>(qkv, rope_cos, rope_sin);
    // 4. attention (HMMA) -> att (bf16 hi/lo)
    attn_mma<<<dim3(NH, SEQ / 64), 128>>>(qkv, offs, noffs, att_hi, att_lo);
    // 5. WO GEMM + residual -> x1 fp32
    gemm_mma<1><<<dim3(HIDDEN/BN, SEQ/BM), 256, GEMM_SMEM>>>(
        att_hi, att_lo, wo_hi, wo_lo, wo_b, x,
        x1, nullptr, nullptr, SEQ, HIDDEN, HIDDEN);
    // 6. LN1 -> h2 (bf16 hi/lo)
    ln_kernel<<<SEQ, 256>>>(x1, norm1_w, norm1_b, h2_hi, h2_lo);
    // 7. UP GEMM + GELU -> u (bf16 hi/lo)
    gemm_mma<2><<<dim3(MLP/BN, SEQ/BM), 256, GEMM_SMEM>>>(
        h2_hi, h2_lo, upw_hi, upw_lo, up_b, nullptr,
        nullptr, u_hi, u_lo, SEQ, MLP, HIDDEN);
    // 8. DOWN GEMM + residual -> out fp32
    gemm_mma<1><<<dim3(HIDDEN/BN, SEQ/BM), 256, GEMM_SMEM>>>(
        u_hi, u_lo, dnw_hi, dnw_lo, down_b, x1,
        out, nullptr, nullptr, SEQ, HIDDEN, MLP);
}

// round 5
// speedup vs baseline: 7.4669x; 1.2724x over previous
#include <cuda_runtime.h>
#include <cuda_fp16.h>
#include <math.h>
#include <stdint.h>

#define SEQ    2048
#define HIDDEN 1024
#define MLP    4096
#define NH     16
#define HD     64

// ---------------- scratch (device globals: allocation-free) ----------------
__device__ __half g_h_hi [SEQ * HIDDEN];
__device__ __half g_h_lo [SEQ * HIDDEN];
__device__ float  g_qkv  [SEQ * 3 * HIDDEN];
__device__ __half g_att_hi[SEQ * HIDDEN];
__device__ __half g_att_lo[SEQ * HIDDEN];
__device__ float  g_x1  [SEQ * HIDDEN];
__device__ __half g_h2_hi[SEQ * HIDDEN];
__device__ __half g_h2_lo[SEQ * HIDDEN];
__device__ __half g_u_hi [SEQ * MLP];
__device__ __half g_u_lo [SEQ * MLP];
__device__ __half g_wqkv [3 * HIDDEN * HIDDEN];
__device__ __half g_wo   [HIDDEN * HIDDEN];
__device__ __half g_upw  [MLP * HIDDEN];
__device__ __half g_dnw  [HIDDEN * MLP];

// ---------------- helpers ----------------------------------------------------
__device__ __forceinline__ uint32_t smem_u32(const void* p) {
    uint32_t a;
    asm("{ .reg .u64 t; cvta.to.shared.u64 t, %1; cvt.u32.u64 %0, t; }"
        : "=r"(a) : "l"(p));
    return a;
}
__device__ __forceinline__ void cp16(uint32_t saddr, const void* gptr) {
    asm volatile("cp.async.cg.shared.global [%0], [%1], 16;"
                 :: "r"(saddr), "l"(gptr));
}
__device__ __forceinline__ void cp_commit() {
    asm volatile("cp.async.commit_group;");
}
__device__ __forceinline__ void cp_wait1() {
    asm volatile("cp.async.wait_group 1;");
}
__device__ __forceinline__ void cp_wait0() {
    asm volatile("cp.async.wait_group 0;");
}
__device__ __forceinline__ void mma16816(float* c, const uint32_t* a, const uint32_t* b) {
    asm volatile(
        "mma.sync.aligned.m16n8k16.row.col.f32.f16.f16.f32 "
        "{%0,%1,%2,%3}, {%4,%5,%6,%7}, {%8,%9}, {%0,%1,%2,%3};"
        : "+f"(c[0]), "+f"(c[1]), "+f"(c[2]), "+f"(c[3])
        : "r"(a[0]), "r"(a[1]), "r"(a[2]), "r"(a[3]), "r"(b[0]), "r"(b[1]));
}
__device__ __forceinline__ void ldsm4(uint32_t* r, uint32_t a) {
    asm volatile("ldmatrix.sync.aligned.m8n8.x4.shared.b16 {%0,%1,%2,%3}, [%4];"
                 : "=r"(r[0]), "=r"(r[1]), "=r"(r[2]), "=r"(r[3]) : "r"(a));
}
__device__ __forceinline__ void ldsm2(uint32_t* r, uint32_t a) {
    asm volatile("ldmatrix.sync.aligned.m8n8.x2.shared.b16 {%0,%1}, [%2];"
                 : "=r"(r[0]), "=r"(r[1]) : "r"(a));
}
__device__ __forceinline__ void ldsm2t(uint32_t* r, uint32_t a) {
    asm volatile("ldmatrix.sync.aligned.m8n8.x2.trans.shared.b16 {%0,%1}, [%2];"
                 : "=r"(r[0]), "=r"(r[1]) : "r"(a));
}
__device__ __forceinline__ void hiloh(float v, __half& h, __half& l) {
    h = __float2half_rn(v);
    l = __float2half_rn(v - __half2float(h));
}
__device__ __forceinline__ uint32_t pack_hilo(float x, float y, uint32_t& lo) {
    __half hx, lx, hy, ly;
    hiloh(x, hx, lx); hiloh(y, hy, ly);
    __half2 hp = {hx, hy}, lp = {lx, ly};
    lo = *(uint32_t*)&lp;
    return *(uint32_t*)&hp;
}
__device__ __forceinline__ float gelu_tanh(float v) {
    float c = 0.7978845608028654f * (v + 0.044715f * v * v * v);
    return 0.5f * v * (1.f + tanhf(c));
}

// ---------------- weight conversion (fp32 -> fp16 single) --------------------
__global__ __launch_bounds__(256) void conv_kernel(
    const float* __restrict__ src, __half* __restrict__ dst, int n4)
{
    int i = blockIdx.x * 256 + threadIdx.x;
    if (i >= n4) return;
    float4 v = ((const float4*)src)[i];
    __half h[4];
    h[0] = __float2half_rn(v.x); h[1] = __float2half_rn(v.y);
    h[2] = __float2half_rn(v.z); h[3] = __float2half_rn(v.w);
    *(uint2*)&dst[i * 4] = *(uint2*)h;
}

// ---------------- LayerNorm (writes fp16 hi/lo) -------------------------------
__global__ __launch_bounds__(256) void ln_kernel(
    const float* __restrict__ x, const float* __restrict__ w,
    const float* __restrict__ b, __half* __restrict__ yh,
    __half* __restrict__ yl)
{
    int row = blockIdx.x;
    int tid = threadIdx.x;
    float4 v = *(const float4*)&x[row * HIDDEN + tid * 4];
    float s  = v.x + v.y + v.z + v.w;
    float ss = v.x*v.x + v.y*v.y + v.z*v.z + v.w*v.w;
#pragma unroll
    for (int o = 16; o > 0; o >>= 1) {
        s  += __shfl_xor_sync(0xffffffffu, s,  o);
        ss += __shfl_xor_sync(0xffffffffu, ss, o);
    }
    __shared__ float2 red[8];
    int wid = tid >> 5, lane = tid & 31;
    if (lane == 0) red[wid] = make_float2(s, ss);
    __syncthreads();
    if (tid < 32) {
        float2 t = (tid < 8) ? red[tid] : make_float2(0.f, 0.f);
        s = t.x; ss = t.y;
#pragma unroll
        for (int o = 4; o > 0; o >>= 1) {
            s  += __shfl_xor_sync(0xffffffffu, s,  o);
            ss += __shfl_xor_sync(0xffffffffu, ss, o);
        }
        if (lane == 0) red[0] = make_float2(s, ss);
    }
    __syncthreads();
    float mean = red[0].x * (1.f / HIDDEN);
    float var  = red[0].y * (1.f / HIDDEN) - mean * mean;
    float rstd = rsqrtf(var + 1e-5f);
    float4 w4 = *(const float4*)&w[tid * 4];
    float4 b4 = *(const float4*)&b[tid * 4];
    float o0 = (v.x - mean) * rstd * w4.x + b4.x;
    float o1 = (v.y - mean) * rstd * w4.y + b4.y;
    float o2 = (v.z - mean) * rstd * w4.z + b4.z;
    float o3 = (v.w - mean) * rstd * w4.w + b4.w;
    __half h[4], l[4];
    hiloh(o0, h[0], l[0]); hiloh(o1, h[1], l[1]);
    hiloh(o2, h[2], l[2]); hiloh(o3, h[3], l[3]);
    *(uint2*)&yh[row * HIDDEN + tid * 4] = *(uint2*)h;
    *(uint2*)&yl[row * HIDDEN + tid * 4] = *(uint2*)l;
}

// ---------------- HMMA GEMM (NT): C = (Ah+Al) @ B^T + bias -------------------
// A split fp16 hi/lo (exact), B single fp16. 2 MMAs per mn-tile per k-step.
#define BM 128
#define BN 128
#define BK 32
#define ROWB 80
#define MATB (128 * ROWB)
#define STAGEB (3 * MATB)
#define GEMM_SMEM (2 * STAGEB)

template <int EPI>
__global__ __launch_bounds__(256) void gemm_mma(
    const __half* __restrict__ Ah, const __half* __restrict__ Al,
    const __half* __restrict__ B,
    const float* __restrict__ bias, const float* __restrict__ res,
    float* __restrict__ C, __half* __restrict__ Chi,
    __half* __restrict__ Clo, int M, int N, int K)
{
    extern __shared__ char smem[];
    uint32_t sb = smem_u32(smem);
    int tid = threadIdx.x, wid = tid >> 5, lane = tid & 31;
    int bm = blockIdx.y * BM, bn = blockIdx.x * BN;
    int wm = (wid >> 2) * 64, wn = (wid & 3) * 32;
    int g = lane >> 2, t4 = lane & 3;

    float acc[4][4][4];
#pragma unroll
    for (int i = 0; i < 4; i++)
#pragma unroll
        for (int j = 0; j < 4; j++)
#pragma unroll
            for (int q = 0; q < 4; q++) acc[i][j][q] = 0.f;

    int lr0 = tid >> 2;          // 0..63
    int lch = (tid & 3) * 8;     // halves offset (16B chunk)

    // ldmatrix lane address components
    int arow = (lane & 7) + ((lane >> 3) & 1) * 8;
    int acol = ((lane >> 4) & 1) * 8;
    int brow = ((lane >> 4) & 1) * 8 + (lane & 7);
    int bcol = ((lane >> 3) & 1) * 8;

    int T = K / BK;
    {
#pragma unroll
        for (int i = 0; i < 2; i++) {
            int r = lr0 + i * 64;
            uint32_t so = sb + r * ROWB + lch * 2;
            size_t ga = (size_t)(bm + r) * K + lch;
            size_t gb = (size_t)(bn + r) * K + lch;
            cp16(so,          Ah + ga);
            cp16(so + MATB,   Al + ga);
            cp16(so + 2*MATB, B + gb);
        }
        cp_commit();
    }

    for (int t = 0; t < T; t++) {
        if (t + 1 < T) {
            int s = (t + 1) & 1;
            int k0 = (t + 1) * BK;
#pragma unroll
            for (int i = 0; i < 2; i++) {
                int r = lr0 + i * 64;
                uint32_t so = sb + s * STAGEB + r * ROWB + lch * 2;
                size_t ga = (size_t)(bm + r) * K + k0 + lch;
                size_t gb = (size_t)(bn + r) * K + k0 + lch;
                cp16(so,          Ah + ga);
                cp16(so + MATB,   Al + ga);
                cp16(so + 2*MATB, B + gb);
            }
            cp_commit();
            cp_wait1();
        } else {
            cp_wait0();
        }
        __syncthreads();

        uint32_t base = sb + (t & 1) * STAGEB;
#pragma unroll
        for (int ks = 0; ks < 2; ks++) {
            uint32_t a_hi[4][4], a_lo[4][4], b[4][2];
#pragma unroll
            for (int mi = 0; mi < 4; mi++) {
                uint32_t aaddr = base + (wm + mi * 16 + arow) * ROWB +
                                 (ks * 16 + acol) * 2;
                ldsm4(a_hi[mi], aaddr);
                ldsm4(a_lo[mi], aaddr + MATB);
            }
#pragma unroll
            for (int np = 0; np < 2; np++) {
                uint32_t tmp[4];
                uint32_t baddr = base + 2 * MATB +
                                 (wn + np * 16 + brow) * ROWB +
                                 (ks * 16 + bcol) * 2;
                ldsm4(tmp, baddr);
                b[2*np][0] = tmp[0]; b[2*np][1] = tmp[1];
                b[2*np+1][0] = tmp[2]; b[2*np+1][1] = tmp[3];
            }
#pragma unroll
            for (int mi = 0; mi < 4; mi++)
#pragma unroll
                for (int ni = 0; ni < 4; ni++) {
                    mma16816(acc[mi][ni], a_hi[mi], b[ni]);
                    mma16816(acc[mi][ni], a_lo[mi], b[ni]);
                }
        }
        __syncthreads();
    }

#pragma unroll
    for (int mi = 0; mi < 4; mi++) {
#pragma unroll
        for (int ni = 0; ni < 4; ni++) {
            int n0 = bn + wn + ni * 8 + 2 * t4;
            float2 b2 = *(const float2*)&bias[n0];
            float v0 = acc[mi][ni][0] + b2.x;
            float v1 = acc[mi][ni][1] + b2.y;
            float v2 = acc[mi][ni][2] + b2.x;
            float v3 = acc[mi][ni][3] + b2.y;
            int m0 = bm + wm + mi * 16 + g;
            size_t off0 = (size_t)m0 * N + n0;
            size_t off1 = (size_t)(m0 + 8) * N + n0;
            if (EPI == 1) {
                float2 r0 = *(const float2*)&res[off0];
                float2 r1 = *(const float2*)&res[off1];
                v0 += r0.x; v1 += r0.y; v2 += r1.x; v3 += r1.y;
            }
            if (EPI == 2) {
                v0 = gelu_tanh(v0); v1 = gelu_tanh(v1);
                v2 = gelu_tanh(v2); v3 = gelu_tanh(v3);
                uint32_t lo0, lo1;
                uint32_t hi0 = pack_hilo(v0, v1, lo0);
                uint32_t hi1 = pack_hilo(v2, v3, lo1);
                *(uint32_t*)&Chi[off0] = hi0;
                *(uint32_t*)&Clo[off0] = lo0;
                *(uint32_t*)&Chi[off1] = hi1;
                *(uint32_t*)&Clo[off1] = lo1;
            } else {
                *(float2*)&C[off0] = make_float2(v0, v1);
                *(float2*)&C[off1] = make_float2(v2, v3);
            }
        }
    }
}

// ---------------- Attention: HMMA flash, fused RoPE, BQ=64, BKt=64 -----------
// Segment "mask" is an ADDITIVE +1.0 bias. Q/P split fp16 hi/lo (2-MMA),
// K/V single fp16. RoPE applied on the fly to Q and K loads.
#define KROW 144

__global__ __launch_bounds__(128) void attn_mma(
    const float* __restrict__ qkv, const float* __restrict__ cs,
    const float* __restrict__ sn, const int* __restrict__ offs, int noffs,
    __half* __restrict__ oh, __half* __restrict__ ol)
{
    __shared__ __align__(16) char sK[64 * KROW];
    __shared__ __align__(16) char sV[64 * KROW];
    __shared__ int segk[64];

    int head = blockIdx.x, qb = blockIdx.y;
    int tid  = threadIdx.x;
    int w = tid >> 5, lane = tid & 31;
    int g = lane >> 2, t4 = lane & 3;

    uint32_t aK = smem_u32(sK), aV = smem_u32(sV);

    // ---- Q fragments: load fp32, RoPE, scale 1/8, split hi/lo ----
    uint32_t qh[4][4], ql[4][4];
    int qr0 = qb * 64 + w * 16 + g;
    {
        const float* q0 = qkv + (size_t)qr0 * 3072 + head * 64;
        const float* q8 = q0 + 8 * 3072;
        const float* cs0 = cs + qr0 * 32;
        const float* sn0 = sn + qr0 * 32;
        const float* cs8 = cs0 + 8 * 32;
        const float* sn8 = sn0 + 8 * 32;
#pragma unroll
        for (int kk = 0; kk < 4; kk++) {
            int c0 = kk * 16 + 2 * t4;
            int p0 = c0 >> 1, p1 = (c0 + 8) >> 1;
            float2 v00 = *(const float2*)(q0 + c0);
            float2 v10 = *(const float2*)(q8 + c0);
            float2 v01 = *(const float2*)(q0 + c0 + 8);
            float2 v11 = *(const float2*)(q8 + c0 + 8);
            float c00 = cs0[p0], s00 = sn0[p0];
            float c80 = cs8[p0], s80 = sn8[p0];
            float c01 = cs0[p1], s01 = sn0[p1];
            float c81 = cs8[p1], s81 = sn8[p1];
            float r00 = v00.x * c00 - v00.y * s00, i00 = v00.x * s00 + v00.y * c00;
            float r10 = v10.x * c80 - v10.y * s80, i10 = v10.x * s80 + v10.y * c80;
            float r01 = v01.x * c01 - v01.y * s01, i01 = v01.x * s01 + v01.y * c01;
            float r11 = v11.x * c81 - v11.y * s81, i11 = v11.x * s81 + v11.y * c81;
            qh[kk][0] = pack_hilo(r00 * 0.125f, i00 * 0.125f, ql[kk][0]);
            qh[kk][1] = pack_hilo(r10 * 0.125f, i10 * 0.125f, ql[kk][1]);
            qh[kk][2] = pack_hilo(r01 * 0.125f, i01 * 0.125f, ql[kk][2]);
            qh[kk][3] = pack_hilo(r11 * 0.125f, i11 * 0.125f, ql[kk][3]);
        }
    }
    int segq0 = 0, segq8 = 0;
    for (int t = 0; t < noffs; t++) {
        if (offs[t] <= qr0)     segq0++;
        if (offs[t] <= qr0 + 8) segq8++;
    }
    segq0--; segq8--;

    float o[8][4];
#pragma unroll
    for (int nt = 0; nt < 8; nt++)
#pragma unroll
        for (int q = 0; q < 4; q++) o[nt][q] = 0.f;
    float m0 = -1e30f, m8 = -1e30f, l0 = 0.f, l8 = 0.f;

    for (int kt = 0; kt < SEQ / 64; kt++) {
        __syncthreads();
        // K (with RoPE) and V tiles -> single fp16
#pragma unroll
        for (int i = 0; i < 8; i++) {
            int fid = tid + i * 128;
            int row = fid >> 4;
            int c4  = (fid & 15) * 4;
            int pos = kt * 64 + row;
            const float* kp = qkv + (size_t)pos * 3072 + 1024 + head * 64 + c4;
            float4 kv = *(const float4*)kp;
            float4 vv = *(const float4*)(kp + 1024);
            int p0 = c4 >> 1;
            float c0 = cs[pos * 32 + p0],     s0 = sn[pos * 32 + p0];
            float c1 = cs[pos * 32 + p0 + 1], s1 = sn[pos * 32 + p0 + 1];
            float kr0 = kv.x * c0 - kv.y * s0, ki0 = kv.x * s0 + kv.y * c0;
            float kr1 = kv.z * c1 - kv.w * s1, ki1 = kv.z * s1 + kv.w * c1;
            __half kh[4], vh4[4];
            kh[0] = __float2half_rn(kr0); kh[1] = __float2half_rn(ki0);
            kh[2] = __float2half_rn(kr1); kh[3] = __float2half_rn(ki1);
            vh4[0] = __float2half_rn(vv.x); vh4[1] = __float2half_rn(vv.y);
            vh4[2] = __float2half_rn(vv.z); vh4[3] = __float2half_rn(vv.w);
            int so = row * KROW + c4 * 2;
            *(uint2*)(sK + so) = *(uint2*)kh;
            *(uint2*)(sV + so) = *(uint2*)vh4;
        }
        if (tid < 64) {
            int kg = kt * 64 + tid;
            int c2 = 0;
            for (int t = 0; t < noffs; t++) if (offs[t] <= kg) c2++;
            segk[tid] = c2 - 1;
        }
        __syncthreads();

        // ---- scores S = Q @ K^T (2-MMA) ----
        float s[8][4];
#pragma unroll
        for (int nt = 0; nt < 8; nt++)
#pragma unroll
            for (int q = 0; q < 4; q++) s[nt][q] = 0.f;
#pragma unroll
        for (int kk = 0; kk < 4; kk++) {
#pragma unroll
            for (int nt = 0; nt < 8; nt++) {
                uint32_t off = (uint32_t)((nt * 8 + (lane & 7)) * KROW +
                                          (kk * 16 + ((lane >> 3) & 1) * 8) * 2);
                uint32_t bh[2];
                ldsm2(bh, aK + off);
                mma16816(s[nt], qh[kk], bh);
                mma16816(s[nt], ql[kk], bh);
            }
        }
        // ---- +1.0 segment bias, online softmax ----
        float mt0 = -1e30f, mt8 = -1e30f;
#pragma unroll
        for (int nt = 0; nt < 8; nt++) {
            int sc0 = segk[nt * 8 + 2 * t4];
            int sc1 = segk[nt * 8 + 2 * t4 + 1];
            s[nt][0] += (segq0 == sc0) ? 1.f : 0.f;
            s[nt][1] += (segq0 == sc1) ? 1.f : 0.f;
            s[nt][2] += (segq8 == sc0) ? 1.f : 0.f;
            s[nt][3] += (segq8 == sc1) ? 1.f : 0.f;
            mt0 = fmaxf(mt0, fmaxf(s[nt][0], s[nt][1]));
            mt8 = fmaxf(mt8, fmaxf(s[nt][2], s[nt][3]));
        }
        mt0 = fmaxf(mt0, __shfl_xor_sync(0xffffffffu, mt0, 1));
        mt0 = fmaxf(mt0, __shfl_xor_sync(0xffffffffu, mt0, 2));
        mt8 = fmaxf(mt8, __shfl_xor_sync(0xffffffffu, mt8, 1));
        mt8 = fmaxf(mt8, __shfl_xor_sync(0xffffffffu, mt8, 2));
        float mn0 = fmaxf(m0, mt0), mn8 = fmaxf(m8, mt8);
        float corr0 = __expf(m0 - mn0), corr8 = __expf(m8 - mn8);
        m0 = mn0; m8 = mn8;
        float lp0 = 0.f, lp8 = 0.f;
#pragma unroll
        for (int nt = 0; nt < 8; nt++) {
            s[nt][0] = __expf(s[nt][0] - mn0);
            s[nt][1] = __expf(s[nt][1] - mn0);
            s[nt][2] = __expf(s[nt][2] - mn8);
            s[nt][3] = __expf(s[nt][3] - mn8);
            lp0 += s[nt][0] + s[nt][1];
            lp8 += s[nt][2] + s[nt][3];
        }
        lp0 += __shfl_xor_sync(0xffffffffu, lp0, 1);
        lp0 += __shfl_xor_sync(0xffffffffu, lp0, 2);
        lp8 += __shfl_xor_sync(0xffffffffu, lp8, 1);
        lp8 += __shfl_xor_sync(0xffffffffu, lp8, 2);
        l0 = l0 * corr0 + lp0;
        l8 = l8 * corr8 + lp8;
#pragma unroll
        for (int nt = 0; nt < 8; nt++) {
            o[nt][0] *= corr0; o[nt][1] *= corr0;
            o[nt][2] *= corr8; o[nt][3] *= corr8;
        }
        // ---- O += P @ V (2-MMA, P frags built in-register) ----
#pragma unroll
        for (int kk = 0; kk < 4; kk++) {
            uint32_t pah[4], pal[4];
            pah[0] = pack_hilo(s[2*kk][0],   s[2*kk][1],   pal[0]);
            pah[1] = pack_hilo(s[2*kk][2],   s[2*kk][3],   pal[1]);
            pah[2] = pack_hilo(s[2*kk+1][0], s[2*kk+1][1], pal[2]);
            pah[3] = pack_hilo(s[2*kk+1][2], s[2*kk+1][3], pal[3]);
#pragma unroll
            for (int nt = 0; nt < 8; nt++) {
                uint32_t off = (uint32_t)((kk * 16 + (lane & 15)) * KROW + nt * 16);
                uint32_t vh[2];
                ldsm2t(vh, aV + off);
                mma16816(o[nt], pah, vh);
                mma16816(o[nt], pal, vh);
            }
        }
    }

    float inv0 = 1.f / l0, inv8 = 1.f / l8;
    size_t r0off = (size_t)qr0 * HIDDEN + head * 64;
    size_t r8off = r0off + 8 * HIDDEN;
#pragma unroll
    for (int nt = 0; nt < 8; nt++) {
        int col = nt * 8 + 2 * t4;
        uint32_t lo0, lo1;
        uint32_t hi0 = pack_hilo(o[nt][0] * inv0, o[nt][1] * inv0, lo0);
        uint32_t hi1 = pack_hilo(o[nt][2] * inv8, o[nt][3] * inv8, lo1);
        *(uint32_t*)&oh[r0off + col] = hi0;
        *(uint32_t*)&ol[r0off + col] = lo0;
        *(uint32_t*)&oh[r8off + col] = hi1;
        *(uint32_t*)&ol[r8off + col] = lo1;
    }
}

// ---------------- launch ------------------------------------------------------
extern "C" void kernel_launch(void* const* d_in, const int* in_sizes, int n_in,
                              void* d_out, int out_size)
{
    const float* x        = (const float*)d_in[0];
    const float* rope_cos = (const float*)d_in[1];
    const float* rope_sin = (const float*)d_in[2];
    const float* norm0_w  = (const float*)d_in[3];
    const float* norm0_b  = (const float*)d_in[4];
    const float* norm1_w  = (const float*)d_in[5];
    const float* norm1_b  = (const float*)d_in[6];
    const float* wqkv_w   = (const float*)d_in[7];
    const float* wqkv_b   = (const float*)d_in[8];
    const float* wo_w     = (const float*)d_in[9];
    const float* wo_b     = (const float*)d_in[10];
    const float* up_w     = (const float*)d_in[11];
    const float* up_b     = (const float*)d_in[12];
    const float* down_w   = (const float*)d_in[13];
    const float* down_b   = (const float*)d_in[14];
    const int*   offs     = (const int*)d_in[15];
    int noffs = in_sizes[15];
    float* out = (float*)d_out;

    __half *h_hi, *h_lo, *att_hi, *att_lo, *h2_hi, *h2_lo, *u_hi, *u_lo;
    __half *wqkv, *wo, *upw, *dnw;
    float *qkv, *x1;
    cudaGetSymbolAddress((void**)&h_hi, g_h_hi);
    cudaGetSymbolAddress((void**)&h_lo, g_h_lo);
    cudaGetSymbolAddress((void**)&qkv,  g_qkv);
    cudaGetSymbolAddress((void**)&att_hi, g_att_hi);
    cudaGetSymbolAddress((void**)&att_lo, g_att_lo);
    cudaGetSymbolAddress((void**)&x1,   g_x1);
    cudaGetSymbolAddress((void**)&h2_hi, g_h2_hi);
    cudaGetSymbolAddress((void**)&h2_lo, g_h2_lo);
    cudaGetSymbolAddress((void**)&u_hi, g_u_hi);
    cudaGetSymbolAddress((void**)&u_lo, g_u_lo);
    cudaGetSymbolAddress((void**)&wqkv, g_wqkv);
    cudaGetSymbolAddress((void**)&wo,   g_wo);
    cudaGetSymbolAddress((void**)&upw,  g_upw);
    cudaGetSymbolAddress((void**)&dnw,  g_dnw);

    cudaFuncSetAttribute(gemm_mma<0>, cudaFuncAttributeMaxDynamicSharedMemorySize, GEMM_SMEM);
    cudaFuncSetAttribute(gemm_mma<1>, cudaFuncAttributeMaxDynamicSharedMemorySize, GEMM_SMEM);
    cudaFuncSetAttribute(gemm_mma<2>, cudaFuncAttributeMaxDynamicSharedMemorySize, GEMM_SMEM);

    conv_kernel<<<(3*HIDDEN*HIDDEN/4 + 255)/256, 256>>>(wqkv_w, wqkv, 3*HIDDEN*HIDDEN/4);
    conv_kernel<<<(HIDDEN*HIDDEN/4 + 255)/256, 256>>>(wo_w, wo, HIDDEN*HIDDEN/4);
    conv_kernel<<<(MLP*HIDDEN/4 + 255)/256, 256>>>(up_w, upw, MLP*HIDDEN/4);
    conv_kernel<<<(HIDDEN*MLP/4 + 255)/256, 256>>>(down_w, dnw, HIDDEN*MLP/4);

    // 1. LN0 -> h (fp16 hi/lo)
    ln_kernel<<<SEQ, 256>>>(x, norm0_w, norm0_b, h_hi, h_lo);
    // 2. QKV GEMM -> fp32 qkv (un-roped; rope fused into attention loads)
    gemm_mma<0><<<dim3(3*HIDDEN/BN, SEQ/BM), 256, GEMM_SMEM>>>(
        h_hi, h_lo, wqkv, wqkv_b, nullptr,
        qkv, nullptr, nullptr, SEQ, 3*HIDDEN, HIDDEN);
    // 3. attention (HMMA, fused RoPE) -> att (fp16 hi/lo)
    attn_mma<<<dim3(NH, SEQ / 64), 128>>>(qkv, rope_cos, rope_sin, offs, noffs,
                                          att_hi, att_lo);
    // 4. WO GEMM + residual -> x1 fp32
    gemm_mma<1><<<dim3(HIDDEN/BN, SEQ/BM), 256, GEMM_SMEM>>>(
        att_hi, att_lo, wo, wo_b, x,
        x1, nullptr, nullptr, SEQ, HIDDEN, HIDDEN);
    // 5. LN1 -> h2 (fp16 hi/lo)
    ln_kernel<<<SEQ, 256>>>(x1, norm1_w, norm1_b, h2_hi, h2_lo);
    // 6. UP GEMM + GELU -> u (fp16 hi/lo)
    gemm_mma<2><<<dim3(MLP/BN, SEQ/BM), 256, GEMM_SMEM>>>(
        h2_hi, h2_lo, upw, up_b, nullptr,
        nullptr, u_hi, u_lo, SEQ, MLP, HIDDEN);
    // 7. DOWN GEMM + residual -> out fp32
    gemm_mma<1><<<dim3(HIDDEN/BN, SEQ/BM), 256, GEMM_SMEM>>>(
        u_hi, u_lo, dnw, down_b, x1,
        out, nullptr, nullptr, SEQ, HIDDEN, MLP);
}

// round 6
// speedup vs baseline: 11.8412x; 1.5858x over previous
#include <cuda_runtime.h>
#include <cuda_fp16.h>
#include <math.h>
#include <stdint.h>

#define SEQ    2048
#define HIDDEN 1024
#define MLP    4096
#define NH     16
#define HD     64

// ---------------- scratch (device globals: allocation-free) ----------------
__device__ __half g_h   [SEQ * HIDDEN];        // ln0 out (fp16)
__device__ __half g_qkvh[SEQ * 3 * HIDDEN];    // qkv, rope applied, q pre-scaled
__device__ __half g_att [SEQ * HIDDEN];        // attention out (fp16)
__device__ float  g_x1  [SEQ * HIDDEN];        // x + wo(att)  (fp32)
__device__ __half g_h2  [SEQ * HIDDEN];        // ln1 out (fp16)
__device__ __half g_u   [SEQ * MLP];           // gelu(up) (fp16)
__device__ __half g_wqkv[3 * HIDDEN * HIDDEN];
__device__ __half g_wo  [HIDDEN * HIDDEN];
__device__ __half g_upw [MLP * HIDDEN];
__device__ __half g_dnw [HIDDEN * MLP];

// ---------------- helpers ----------------------------------------------------
__device__ __forceinline__ uint32_t smem_u32(const void* p) {
    uint32_t a;
    asm("{ .reg .u64 t; cvta.to.shared.u64 t, %1; cvt.u32.u64 %0, t; }"
        : "=r"(a) : "l"(p));
    return a;
}
__device__ __forceinline__ void cp16(uint32_t saddr, const void* gptr) {
    asm volatile("cp.async.cg.shared.global [%0], [%1], 16;"
                 :: "r"(saddr), "l"(gptr));
}
__device__ __forceinline__ void cp_commit() {
    asm volatile("cp.async.commit_group;");
}
__device__ __forceinline__ void cp_wait1() {
    asm volatile("cp.async.wait_group 1;");
}
__device__ __forceinline__ void cp_wait0() {
    asm volatile("cp.async.wait_group 0;");
}
__device__ __forceinline__ void mma16816(float* c, const uint32_t* a, const uint32_t* b) {
    asm volatile(
        "mma.sync.aligned.m16n8k16.row.col.f32.f16.f16.f32 "
        "{%0,%1,%2,%3}, {%4,%5,%6,%7}, {%8,%9}, {%0,%1,%2,%3};"
        : "+f"(c[0]), "+f"(c[1]), "+f"(c[2]), "+f"(c[3])
        : "r"(a[0]), "r"(a[1]), "r"(a[2]), "r"(a[3]), "r"(b[0]), "r"(b[1]));
}
__device__ __forceinline__ void ldsm4(uint32_t* r, uint32_t a) {
    asm volatile("ldmatrix.sync.aligned.m8n8.x4.shared.b16 {%0,%1,%2,%3}, [%4];"
                 : "=r"(r[0]), "=r"(r[1]), "=r"(r[2]), "=r"(r[3]) : "r"(a));
}
__device__ __forceinline__ void ldsm2(uint32_t* r, uint32_t a) {
    asm volatile("ldmatrix.sync.aligned.m8n8.x2.shared.b16 {%0,%1}, [%2];"
                 : "=r"(r[0]), "=r"(r[1]) : "r"(a));
}
__device__ __forceinline__ void ldsm2t(uint32_t* r, uint32_t a) {
    asm volatile("ldmatrix.sync.aligned.m8n8.x2.trans.shared.b16 {%0,%1}, [%2];"
                 : "=r"(r[0]), "=r"(r[1]) : "r"(a));
}
__device__ __forceinline__ uint32_t pack2h(float x, float y) {
    __half2 h = __floats2half2_rn(x, y);
    return *(uint32_t*)&h;
}
__device__ __forceinline__ float gelu_tanh(float v) {
    float c = 0.7978845608028654f * (v + 0.044715f * v * v * v);
    return 0.5f * v * (1.f + tanhf(c));
}

// ---------------- weight conversion (fp32 -> fp16) ---------------------------
__global__ __launch_bounds__(256) void conv_kernel(
    const float* __restrict__ src, __half* __restrict__ dst, int n4)
{
    int i = blockIdx.x * 256 + threadIdx.x;
    if (i >= n4) return;
    float4 v = ((const float4*)src)[i];
    __half h[4];
    h[0] = __float2half_rn(v.x); h[1] = __float2half_rn(v.y);
    h[2] = __float2half_rn(v.z); h[3] = __float2half_rn(v.w);
    *(uint2*)&dst[i * 4] = *(uint2*)h;
}

// ---------------- LayerNorm (fp32 in, fp16 out) -------------------------------
__global__ __launch_bounds__(256) void ln_kernel(
    const float* __restrict__ x, const float* __restrict__ w,
    const float* __restrict__ b, __half* __restrict__ y)
{
    int row = blockIdx.x;
    int tid = threadIdx.x;
    float4 v = *(const float4*)&x[row * HIDDEN + tid * 4];
    float s  = v.x + v.y + v.z + v.w;
    float ss = v.x*v.x + v.y*v.y + v.z*v.z + v.w*v.w;
#pragma unroll
    for (int o = 16; o > 0; o >>= 1) {
        s  += __shfl_xor_sync(0xffffffffu, s,  o);
        ss += __shfl_xor_sync(0xffffffffu, ss, o);
    }
    __shared__ float2 red[8];
    int wid = tid >> 5, lane = tid & 31;
    if (lane == 0) red[wid] = make_float2(s, ss);
    __syncthreads();
    if (tid < 32) {
        float2 t = (tid < 8) ? red[tid] : make_float2(0.f, 0.f);
        s = t.x; ss = t.y;
#pragma unroll
        for (int o = 4; o > 0; o >>= 1) {
            s  += __shfl_xor_sync(0xffffffffu, s,  o);
            ss += __shfl_xor_sync(0xffffffffu, ss, o);
        }
        if (lane == 0) red[0] = make_float2(s, ss);
    }
    __syncthreads();
    float mean = red[0].x * (1.f / HIDDEN);
    float var  = red[0].y * (1.f / HIDDEN) - mean * mean;
    float rstd = rsqrtf(var + 1e-5f);
    float4 w4 = *(const float4*)&w[tid * 4];
    float4 b4 = *(const float4*)&b[tid * 4];
    __half h[4];
    h[0] = __float2half_rn((v.x - mean) * rstd * w4.x + b4.x);
    h[1] = __float2half_rn((v.y - mean) * rstd * w4.y + b4.y);
    h[2] = __float2half_rn((v.z - mean) * rstd * w4.z + b4.z);
    h[3] = __float2half_rn((v.w - mean) * rstd * w4.w + b4.w);
    *(uint2*)&y[row * HIDDEN + tid * 4] = *(uint2*)h;
}

// ---------------- HMMA GEMM (NT): C = A @ B^T + bias -------------------------
// A, B single fp16. 1 MMA per mn-tile per k-step.
// EPI: 1 = +bias+res -> fp32 C; 2 = +bias,GELU -> fp16 Ch;
//      3 = +bias, RoPE(q,k)+q-scale -> fp16 Ch (QKV layout N=3072)
#define BM 128
#define BN 128
#define BK 32
#define ROWB 80
#define MATB (128 * ROWB)
#define STAGEB (2 * MATB)
#define GEMM_SMEM (2 * STAGEB)

template <int EPI>
__global__ __launch_bounds__(256) void gemm_mma(
    const __half* __restrict__ A, const __half* __restrict__ B,
    const float* __restrict__ bias, const float* __restrict__ res,
    const float* __restrict__ cs, const float* __restrict__ sn,
    float* __restrict__ C, __half* __restrict__ Ch, int M, int N, int K)
{
    extern __shared__ char smem[];
    uint32_t sb = smem_u32(smem);
    int tid = threadIdx.x, wid = tid >> 5, lane = tid & 31;
    int bm = blockIdx.y * BM, bn = blockIdx.x * BN;
    int wm = (wid >> 2) * 64, wn = (wid & 3) * 32;
    int g = lane >> 2, t4 = lane & 3;

    float acc[4][4][4];
#pragma unroll
    for (int i = 0; i < 4; i++)
#pragma unroll
        for (int j = 0; j < 4; j++)
#pragma unroll
            for (int q = 0; q < 4; q++) acc[i][j][q] = 0.f;

    int lr0 = tid >> 2;          // 0..63
    int lch = (tid & 3) * 8;     // 16B chunk offset in halves

    int arow = (lane & 7) + ((lane >> 3) & 1) * 8;
    int acol = ((lane >> 4) & 1) * 8;
    int brow = ((lane >> 4) & 1) * 8 + (lane & 7);
    int bcol = ((lane >> 3) & 1) * 8;

    int T = K / BK;
    {
#pragma unroll
        for (int i = 0; i < 2; i++) {
            int r = lr0 + i * 64;
            uint32_t so = sb + r * ROWB + lch * 2;
            cp16(so,        A + (size_t)(bm + r) * K + lch);
            cp16(so + MATB, B + (size_t)(bn + r) * K + lch);
        }
        cp_commit();
    }

    for (int t = 0; t < T; t++) {
        if (t + 1 < T) {
            int s = (t + 1) & 1;
            int k0 = (t + 1) * BK;
#pragma unroll
            for (int i = 0; i < 2; i++) {
                int r = lr0 + i * 64;
                uint32_t so = sb + s * STAGEB + r * ROWB + lch * 2;
                cp16(so,        A + (size_t)(bm + r) * K + k0 + lch);
                cp16(so + MATB, B + (size_t)(bn + r) * K + k0 + lch);
            }
            cp_commit();
            cp_wait1();
        } else {
            cp_wait0();
        }
        __syncthreads();

        uint32_t base = sb + (t & 1) * STAGEB;
#pragma unroll
        for (int ks = 0; ks < 2; ks++) {
            uint32_t a[4][4], b[4][2];
#pragma unroll
            for (int mi = 0; mi < 4; mi++)
                ldsm4(a[mi], base + (wm + mi * 16 + arow) * ROWB +
                             (ks * 16 + acol) * 2);
#pragma unroll
            for (int np = 0; np < 2; np++) {
                uint32_t tmp[4];
                ldsm4(tmp, base + MATB + (wn + np * 16 + brow) * ROWB +
                           (ks * 16 + bcol) * 2);
                b[2*np][0] = tmp[0]; b[2*np][1] = tmp[1];
                b[2*np+1][0] = tmp[2]; b[2*np+1][1] = tmp[3];
            }
#pragma unroll
            for (int mi = 0; mi < 4; mi++)
#pragma unroll
                for (int ni = 0; ni < 4; ni++)
                    mma16816(acc[mi][ni], a[mi], b[ni]);
        }
        __syncthreads();
    }

#pragma unroll
    for (int mi = 0; mi < 4; mi++) {
#pragma unroll
        for (int ni = 0; ni < 4; ni++) {
            int n0 = bn + wn + ni * 8 + 2 * t4;
            float2 b2 = *(const float2*)&bias[n0];
            float v0 = acc[mi][ni][0] + b2.x;
            float v1 = acc[mi][ni][1] + b2.y;
            float v2 = acc[mi][ni][2] + b2.x;
            float v3 = acc[mi][ni][3] + b2.y;
            int m0 = bm + wm + mi * 16 + g;
            size_t off0 = (size_t)m0 * N + n0;
            size_t off1 = (size_t)(m0 + 8) * N + n0;
            if (EPI == 1) {
                float2 r0 = *(const float2*)&res[off0];
                float2 r1 = *(const float2*)&res[off1];
                v0 += r0.x; v1 += r0.y; v2 += r1.x; v3 += r1.y;
                *(float2*)&C[off0] = make_float2(v0, v1);
                *(float2*)&C[off1] = make_float2(v2, v3);
            }
            if (EPI == 2) {
                v0 = gelu_tanh(v0); v1 = gelu_tanh(v1);
                v2 = gelu_tanh(v2); v3 = gelu_tanh(v3);
                *(uint32_t*)&Ch[off0] = pack2h(v0, v1);
                *(uint32_t*)&Ch[off1] = pack2h(v2, v3);
            }
            if (EPI == 3) {
                if (n0 < 2 * HIDDEN) {  // q or k columns: apply RoPE
                    int p = (n0 & 63) >> 1;
                    float c0 = cs[m0 * 32 + p],       s0 = sn[m0 * 32 + p];
                    float c1 = cs[(m0 + 8) * 32 + p], s1 = sn[(m0 + 8) * 32 + p];
                    float r0 = v0 * c0 - v1 * s0, i0 = v0 * s0 + v1 * c0;
                    float r1 = v2 * c1 - v3 * s1, i1 = v2 * s1 + v3 * c1;
                    if (n0 < HIDDEN) {  // q: fold 1/sqrt(hd) = 1/8
                        r0 *= 0.125f; i0 *= 0.125f;
                        r1 *= 0.125f; i1 *= 0.125f;
                    }
                    v0 = r0; v1 = i0; v2 = r1; v3 = i1;
                }
                *(uint32_t*)&Ch[off0] = pack2h(v0, v1);
                *(uint32_t*)&Ch[off1] = pack2h(v2, v3);
            }
        }
    }
}

// ---------------- Attention: HMMA flash, fp16 qkv, cp.async double-buffer ----
#define KROW 144

__global__ __launch_bounds__(128) void attn_mma(
    const __half* __restrict__ qkvh, const int* __restrict__ offs, int noffs,
    __half* __restrict__ o_out)
{
    __shared__ __align__(16) char sK[2][64 * KROW];
    __shared__ __align__(16) char sV[2][64 * KROW];
    __shared__ int segk[2][64];

    int head = blockIdx.x, qb = blockIdx.y;
    int tid  = threadIdx.x;
    int w = tid >> 5, lane = tid & 31;
    int t4 = lane & 3;
    int g = lane >> 2;

    // ---- Q fragments: direct fp16 copies (rope+scale already applied) ----
    uint32_t qh[4][4];
    int qr0 = qb * 64 + w * 16 + g;
    {
        const __half* q0 = qkvh + (size_t)qr0 * 3072 + head * 64;
#pragma unroll
        for (int kk = 0; kk < 4; kk++) {
            int c0 = kk * 16 + 2 * t4;
            qh[kk][0] = *(const uint32_t*)(q0 + c0);
            qh[kk][1] = *(const uint32_t*)(q0 + 8 * 3072 + c0);
            qh[kk][2] = *(const uint32_t*)(q0 + c0 + 8);
            qh[kk][3] = *(const uint32_t*)(q0 + 8 * 3072 + c0 + 8);
        }
    }
    int segq0 = 0, segq8 = 0;
    for (int t = 0; t < noffs; t++) {
        if (offs[t] <= qr0)     segq0++;
        if (offs[t] <= qr0 + 8) segq8++;
    }
    segq0--; segq8--;

    // ---- K/V tile loader: thread t owns one 128B row ----
    auto load_tile = [&](int kt) {
        int buf = kt & 1;
        int row = tid & 63;
        const __half* src = qkvh + (size_t)(kt * 64 + row) * 3072 +
                            ((tid < 64) ? 1024 : 2048) + head * 64;
        uint32_t dst = smem_u32((tid < 64) ? &sK[buf][row * KROW]
                                           : &sV[buf][row * KROW]);
#pragma unroll
        for (int i = 0; i < 8; i++) cp16(dst + i * 16, src + i * 8);
        cp_commit();
        if (tid < 64) {
            int kg = kt * 64 + tid;
            int c2 = 0;
            for (int t = 0; t < noffs; t++) if (offs[t] <= kg) c2++;
            segk[buf][tid] = c2 - 1;
        }
    };

    float o[8][4];
#pragma unroll
    for (int nt = 0; nt < 8; nt++)
#pragma unroll
        for (int q = 0; q < 4; q++) o[nt][q] = 0.f;
    float m0 = -1e30f, m8 = -1e30f, l0 = 0.f, l8 = 0.f;

    load_tile(0);

    for (int kt = 0; kt < SEQ / 64; kt++) {
        int buf = kt & 1;
        cp_wait0();
        __syncthreads();          // tile kt ready; prev buf fully consumed
        if (kt + 1 < SEQ / 64) load_tile(kt + 1);

        uint32_t aK = smem_u32(sK[buf]), aV = smem_u32(sV[buf]);

        // ---- scores S = Q @ K^T ----
        float s[8][4];
#pragma unroll
        for (int nt = 0; nt < 8; nt++)
#pragma unroll
            for (int q = 0; q < 4; q++) s[nt][q] = 0.f;
#pragma unroll
        for (int kk = 0; kk < 4; kk++) {
#pragma unroll
            for (int nt = 0; nt < 8; nt++) {
                uint32_t off = (uint32_t)((nt * 8 + (lane & 7)) * KROW +
                                          (kk * 16 + ((lane >> 3) & 1) * 8) * 2);
                uint32_t bh[2];
                ldsm2(bh, aK + off);
                mma16816(s[nt], qh[kk], bh);
            }
        }
        // ---- +1.0 segment bias, online softmax ----
        float mt0 = -1e30f, mt8 = -1e30f;
#pragma unroll
        for (int nt = 0; nt < 8; nt++) {
            int sc0 = segk[buf][nt * 8 + 2 * t4];
            int sc1 = segk[buf][nt * 8 + 2 * t4 + 1];
            s[nt][0] += (segq0 == sc0) ? 1.f : 0.f;
            s[nt][1] += (segq0 == sc1) ? 1.f : 0.f;
            s[nt][2] += (segq8 == sc0) ? 1.f : 0.f;
            s[nt][3] += (segq8 == sc1) ? 1.f : 0.f;
            mt0 = fmaxf(mt0, fmaxf(s[nt][0], s[nt][1]));
            mt8 = fmaxf(mt8, fmaxf(s[nt][2], s[nt][3]));
        }
        mt0 = fmaxf(mt0, __shfl_xor_sync(0xffffffffu, mt0, 1));
        mt0 = fmaxf(mt0, __shfl_xor_sync(0xffffffffu, mt0, 2));
        mt8 = fmaxf(mt8, __shfl_xor_sync(0xffffffffu, mt8, 1));
        mt8 = fmaxf(mt8, __shfl_xor_sync(0xffffffffu, mt8, 2));
        float mn0 = fmaxf(m0, mt0), mn8 = fmaxf(m8, mt8);
        float corr0 = __expf(m0 - mn0), corr8 = __expf(m8 - mn8);
        m0 = mn0; m8 = mn8;
        float lp0 = 0.f, lp8 = 0.f;
#pragma unroll
        for (int nt = 0; nt < 8; nt++) {
            s[nt][0] = __expf(s[nt][0] - mn0);
            s[nt][1] = __expf(s[nt][1] - mn0);
            s[nt][2] = __expf(s[nt][2] - mn8);
            s[nt][3] = __expf(s[nt][3] - mn8);
            lp0 += s[nt][0] + s[nt][1];
            lp8 += s[nt][2] + s[nt][3];
        }
        lp0 += __shfl_xor_sync(0xffffffffu, lp0, 1);
        lp0 += __shfl_xor_sync(0xffffffffu, lp0, 2);
        lp8 += __shfl_xor_sync(0xffffffffu, lp8, 1);
        lp8 += __shfl_xor_sync(0xffffffffu, lp8, 2);
        l0 = l0 * corr0 + lp0;
        l8 = l8 * corr8 + lp8;
#pragma unroll
        for (int nt = 0; nt < 8; nt++) {
            o[nt][0] *= corr0; o[nt][1] *= corr0;
            o[nt][2] *= corr8; o[nt][3] *= corr8;
        }
        // ---- O += P @ V ----
#pragma unroll
        for (int kk = 0; kk < 4; kk++) {
            uint32_t pa[4];
            pa[0] = pack2h(s[2*kk][0],   s[2*kk][1]);
            pa[1] = pack2h(s[2*kk][2],   s[2*kk][3]);
            pa[2] = pack2h(s[2*kk+1][0], s[2*kk+1][1]);
            pa[3] = pack2h(s[2*kk+1][2], s[2*kk+1][3]);
#pragma unroll
            for (int nt = 0; nt < 8; nt++) {
                uint32_t off = (uint32_t)((kk * 16 + (lane & 15)) * KROW + nt * 16);
                uint32_t vh[2];
                ldsm2t(vh, aV + off);
                mma16816(o[nt], pa, vh);
            }
        }
        __syncthreads();          // done reading buf before next overwrite
    }

    float inv0 = 1.f / l0, inv8 = 1.f / l8;
    size_t r0off = (size_t)qr0 * HIDDEN + head * 64;
    size_t r8off = r0off + 8 * HIDDEN;
#pragma unroll
    for (int nt = 0; nt < 8; nt++) {
        int col = nt * 8 + 2 * t4;
        *(uint32_t*)&o_out[r0off + col] = pack2h(o[nt][0] * inv0, o[nt][1] * inv0);
        *(uint32_t*)&o_out[r8off + col] = pack2h(o[nt][2] * inv8, o[nt][3] * inv8);
    }
}

// ---------------- launch ------------------------------------------------------
extern "C" void kernel_launch(void* const* d_in, const int* in_sizes, int n_in,
                              void* d_out, int out_size)
{
    const float* x        = (const float*)d_in[0];
    const float* rope_cos = (const float*)d_in[1];
    const float* rope_sin = (const float*)d_in[2];
    const float* norm0_w  = (const float*)d_in[3];
    const float* norm0_b  = (const float*)d_in[4];
    const float* norm1_w  = (const float*)d_in[5];
    const float* norm1_b  = (const float*)d_in[6];
    const float* wqkv_w   = (const float*)d_in[7];
    const float* wqkv_b   = (const float*)d_in[8];
    const float* wo_w     = (const float*)d_in[9];
    const float* wo_b     = (const float*)d_in[10];
    const float* up_w     = (const float*)d_in[11];
    const float* up_b     = (const float*)d_in[12];
    const float* down_w   = (const float*)d_in[13];
    const float* down_b   = (const float*)d_in[14];
    const int*   offs     = (const int*)d_in[15];
    int noffs = in_sizes[15];
    float* out = (float*)d_out;

    __half *h, *qkvh, *att, *h2, *u, *wqkv, *wo, *upw, *dnw;
    float *x1;
    cudaGetSymbolAddress((void**)&h,    g_h);
    cudaGetSymbolAddress((void**)&qkvh, g_qkvh);
    cudaGetSymbolAddress((void**)&att,  g_att);
    cudaGetSymbolAddress((void**)&x1,   g_x1);
    cudaGetSymbolAddress((void**)&h2,   g_h2);
    cudaGetSymbolAddress((void**)&u,    g_u);
    cudaGetSymbolAddress((void**)&wqkv, g_wqkv);
    cudaGetSymbolAddress((void**)&wo,   g_wo);
    cudaGetSymbolAddress((void**)&upw,  g_upw);
    cudaGetSymbolAddress((void**)&dnw,  g_dnw);

    cudaFuncSetAttribute(gemm_mma<1>, cudaFuncAttributeMaxDynamicSharedMemorySize, GEMM_SMEM);
    cudaFuncSetAttribute(gemm_mma<2>, cudaFuncAttributeMaxDynamicSharedMemorySize, GEMM_SMEM);
    cudaFuncSetAttribute(gemm_mma<3>, cudaFuncAttributeMaxDynamicSharedMemorySize, GEMM_SMEM);

    conv_kernel<<<(3*HIDDEN*HIDDEN/4 + 255)/256, 256>>>(wqkv_w, wqkv, 3*HIDDEN*HIDDEN/4);
    conv_kernel<<<(HIDDEN*HIDDEN/4 + 255)/256, 256>>>(wo_w, wo, HIDDEN*HIDDEN/4);
    conv_kernel<<<(MLP*HIDDEN/4 + 255)/256, 256>>>(up_w, upw, MLP*HIDDEN/4);
    conv_kernel<<<(HIDDEN*MLP/4 + 255)/256, 256>>>(down_w, dnw, HIDDEN*MLP/4);

    // 1. LN0 -> h (fp16)
    ln_kernel<<<SEQ, 256>>>(x, norm0_w, norm0_b, h);
    // 2. QKV GEMM + fused RoPE + q-scale -> qkvh (fp16)
    gemm_mma<3><<<dim3(3*HIDDEN/BN, SEQ/BM), 256, GEMM_SMEM>>>(
        h, wqkv, wqkv_b, nullptr, rope_cos, rope_sin,
        nullptr, qkvh, SEQ, 3*HIDDEN, HIDDEN);
    // 3. attention -> att (fp16)
    attn_mma<<<dim3(NH, SEQ / 64), 128>>>(qkvh, offs, noffs, att);
    // 4. WO GEMM + residual -> x1 (fp32)
    gemm_mma<1><<<dim3(HIDDEN/BN, SEQ/BM), 256, GEMM_SMEM>>>(
        att, wo, wo_b, x, nullptr, nullptr,
        x1, nullptr, SEQ, HIDDEN, HIDDEN);
    // 5. LN1 -> h2 (fp16)
    ln_kernel<<<SEQ, 256>>>(x1, norm1_w, norm1_b, h2);
    // 6. UP GEMM + GELU -> u (fp16)
    gemm_mma<2><<<dim3(MLP/BN, SEQ/BM), 256, GEMM_SMEM>>>(
        h2, upw, up_b, nullptr, nullptr, nullptr,
        nullptr, u, SEQ, MLP, HIDDEN);
    // 7. DOWN GEMM + residual -> out (fp32)
    gemm_mma<1><<<dim3(HIDDEN/BN, SEQ/BM), 256, GEMM_SMEM>>>(
        u, dnw, down_b, x1, nullptr, nullptr,
        out, nullptr, SEQ, HIDDEN, MLP);
}

// round 7
// speedup vs baseline: 12.1983x; 1.0302x over previous
#include <cuda_runtime.h>
#include <cuda_fp16.h>
#include <math.h>
#include <stdint.h>

#define SEQ    2048
#define HIDDEN 1024
#define MLP    4096
#define NH     16
#define HD     64

// ---------------- scratch (device globals: allocation-free) ----------------
__device__ __half g_h   [SEQ * HIDDEN];
__device__ __half g_qkvh[SEQ * 3 * HIDDEN];
__device__ __half g_att [SEQ * HIDDEN];
__device__ float  g_x1  [SEQ * HIDDEN];
__device__ __half g_h2  [SEQ * HIDDEN];
__device__ __half g_u   [SEQ * MLP];
__device__ __half g_wqkv[3 * HIDDEN * HIDDEN];
__device__ __half g_wo  [HIDDEN * HIDDEN];
__device__ __half g_upw [MLP * HIDDEN];
__device__ __half g_dnw [HIDDEN * MLP];

// ---------------- helpers ----------------------------------------------------
__device__ __forceinline__ uint32_t smem_u32(const void* p) {
    uint32_t a;
    asm("{ .reg .u64 t; cvta.to.shared.u64 t, %1; cvt.u32.u64 %0, t; }"
        : "=r"(a) : "l"(p));
    return a;
}
__device__ __forceinline__ void cp16(uint32_t saddr, const void* gptr) {
    asm volatile("cp.async.cg.shared.global [%0], [%1], 16;"
                 :: "r"(saddr), "l"(gptr));
}
__device__ __forceinline__ void cp_commit() {
    asm volatile("cp.async.commit_group;");
}
__device__ __forceinline__ void cp_wait1() {
    asm volatile("cp.async.wait_group 1;");
}
__device__ __forceinline__ void cp_wait0() {
    asm volatile("cp.async.wait_group 0;");
}
__device__ __forceinline__ void mma16816(float* c, const uint32_t* a, const uint32_t* b) {
    asm volatile(
        "mma.sync.aligned.m16n8k16.row.col.f32.f16.f16.f32 "
        "{%0,%1,%2,%3}, {%4,%5,%6,%7}, {%8,%9}, {%0,%1,%2,%3};"
        : "+f"(c[0]), "+f"(c[1]), "+f"(c[2]), "+f"(c[3])
        : "r"(a[0]), "r"(a[1]), "r"(a[2]), "r"(a[3]), "r"(b[0]), "r"(b[1]));
}
__device__ __forceinline__ void ldsm4(uint32_t* r, uint32_t a) {
    asm volatile("ldmatrix.sync.aligned.m8n8.x4.shared.b16 {%0,%1,%2,%3}, [%4];"
                 : "=r"(r[0]), "=r"(r[1]), "=r"(r[2]), "=r"(r[3]) : "r"(a));
}
__device__ __forceinline__ void ldsm2(uint32_t* r, uint32_t a) {
    asm volatile("ldmatrix.sync.aligned.m8n8.x2.shared.b16 {%0,%1}, [%2];"
                 : "=r"(r[0]), "=r"(r[1]) : "r"(a));
}
__device__ __forceinline__ void ldsm2t(uint32_t* r, uint32_t a) {
    asm volatile("ldmatrix.sync.aligned.m8n8.x2.trans.shared.b16 {%0,%1}, [%2];"
                 : "=r"(r[0]), "=r"(r[1]) : "r"(a));
}
__device__ __forceinline__ uint32_t pack2h(float x, float y) {
    __half2 h = __floats2half2_rn(x, y);
    return *(uint32_t*)&h;
}
__device__ __forceinline__ float gelu_tanh(float v) {
    float c = 0.7978845608028654f * (v + 0.044715f * v * v * v);
    return 0.5f * v * (1.f + tanhf(c));
}

// ---------------- weight conversion (fp32 -> fp16) ---------------------------
__global__ __launch_bounds__(256) void conv_kernel(
    const float* __restrict__ src, __half* __restrict__ dst, int n4)
{
    int i = blockIdx.x * 256 + threadIdx.x;
    if (i >= n4) return;
    float4 v = ((const float4*)src)[i];
    __half h[4];
    h[0] = __float2half_rn(v.x); h[1] = __float2half_rn(v.y);
    h[2] = __float2half_rn(v.z); h[3] = __float2half_rn(v.w);
    *(uint2*)&dst[i * 4] = *(uint2*)h;
}

// ---------------- LayerNorm (fp32 in, fp16 out) -------------------------------
__global__ __launch_bounds__(256) void ln_kernel(
    const float* __restrict__ x, const float* __restrict__ w,
    const float* __restrict__ b, __half* __restrict__ y)
{
    int row = blockIdx.x;
    int tid = threadIdx.x;
    float4 v = *(const float4*)&x[row * HIDDEN + tid * 4];
    float s  = v.x + v.y + v.z + v.w;
    float ss = v.x*v.x + v.y*v.y + v.z*v.z + v.w*v.w;
#pragma unroll
    for (int o = 16; o > 0; o >>= 1) {
        s  += __shfl_xor_sync(0xffffffffu, s,  o);
        ss += __shfl_xor_sync(0xffffffffu, ss, o);
    }
    __shared__ float2 red[8];
    int wid = tid >> 5, lane = tid & 31;
    if (lane == 0) red[wid] = make_float2(s, ss);
    __syncthreads();
    if (tid < 32) {
        float2 t = (tid < 8) ? red[tid] : make_float2(0.f, 0.f);
        s = t.x; ss = t.y;
#pragma unroll
        for (int o = 4; o > 0; o >>= 1) {
            s  += __shfl_xor_sync(0xffffffffu, s,  o);
            ss += __shfl_xor_sync(0xffffffffu, ss, o);
        }
        if (lane == 0) red[0] = make_float2(s, ss);
    }
    __syncthreads();
    float mean = red[0].x * (1.f / HIDDEN);
    float var  = red[0].y * (1.f / HIDDEN) - mean * mean;
    float rstd = rsqrtf(var + 1e-5f);
    float4 w4 = *(const float4*)&w[tid * 4];
    float4 b4 = *(const float4*)&b[tid * 4];
    __half h[4];
    h[0] = __float2half_rn((v.x - mean) * rstd * w4.x + b4.x);
    h[1] = __float2half_rn((v.y - mean) * rstd * w4.y + b4.y);
    h[2] = __float2half_rn((v.z - mean) * rstd * w4.z + b4.z);
    h[3] = __float2half_rn((v.w - mean) * rstd * w4.w + b4.w);
    *(uint2*)&y[row * HIDDEN + tid * 4] = *(uint2*)h;
}

// ---------------- HMMA GEMM (NT): C = A @ B^T + bias -------------------------
// fp16 inputs, 3-stage cp.async pipeline, 1 barrier per k-step.
// BMT: 128 (4 mi) or 64 (2 mi). BN fixed 128.
// EPI: 1 = +bias+res -> fp32; 2 = +bias,GELU -> fp16; 3 = +bias,RoPE -> fp16
#define BK 32
#define ROWB 80
#define NSTG 3

template <int EPI, int BMT>
__global__ __launch_bounds__(256) void gemm_mma(
    const __half* __restrict__ A, const __half* __restrict__ B,
    const float* __restrict__ bias, const float* __restrict__ res,
    const float* __restrict__ cs, const float* __restrict__ sn,
    float* __restrict__ C, __half* __restrict__ Ch, int M, int N, int K)
{
    constexpr int MI = BMT / 32;
    constexpr int STAGE = (BMT + 128) * ROWB;
    constexpr int NLOAD = (BMT + 128) * 4 / 256;

    extern __shared__ char smem[];
    uint32_t sb = smem_u32(smem);
    int tid = threadIdx.x, wid = tid >> 5, lane = tid & 31;
    int bm = blockIdx.y * BMT, bn = blockIdx.x * 128;
    int wm = (wid >> 2) * (MI * 16), wn = (wid & 3) * 32;
    int g = lane >> 2, t4 = lane & 3;

    float acc[MI][4][4];
#pragma unroll
    for (int i = 0; i < MI; i++)
#pragma unroll
        for (int j = 0; j < 4; j++)
#pragma unroll
            for (int q = 0; q < 4; q++) acc[i][j][q] = 0.f;

    int arow = (lane & 7) + ((lane >> 3) & 1) * 8;
    int acol = ((lane >> 4) & 1) * 8;
    int brow = ((lane >> 4) & 1) * 8 + (lane & 7);
    int bcol = ((lane >> 3) & 1) * 8;

    int T = K / BK;
    auto load_stage = [&](int t) {
        uint32_t sbase = sb + (t % NSTG) * STAGE;
        int k0 = t * BK;
#pragma unroll
        for (int i = 0; i < NLOAD; i++) {
            int idx = tid + i * 256;
            int r = idx >> 2, c8 = (idx & 3) * 8;
            const __half* gp = (r < BMT)
                ? A + (size_t)(bm + r) * K + k0 + c8
                : B + (size_t)(bn + (r - BMT)) * K + k0 + c8;
            cp16(sbase + r * ROWB + c8 * 2, gp);
        }
        cp_commit();
    };

    load_stage(0);
    load_stage(1);

    for (int t = 0; t < T; t++) {
        if (t + 1 < T) cp_wait1(); else cp_wait0();
        __syncthreads();
        if (t + 2 < T) load_stage(t + 2);

        uint32_t base = sb + (t % NSTG) * STAGE;
#pragma unroll
        for (int ks = 0; ks < 2; ks++) {
            uint32_t a[MI][4], b[4][2];
#pragma unroll
            for (int mi = 0; mi < MI; mi++)
                ldsm4(a[mi], base + (wm + mi * 16 + arow) * ROWB +
                             (ks * 16 + acol) * 2);
#pragma unroll
            for (int np = 0; np < 2; np++) {
                uint32_t tmp[4];
                ldsm4(tmp, base + BMT * ROWB + (wn + np * 16 + brow) * ROWB +
                           (ks * 16 + bcol) * 2);
                b[2*np][0] = tmp[0]; b[2*np][1] = tmp[1];
                b[2*np+1][0] = tmp[2]; b[2*np+1][1] = tmp[3];
            }
#pragma unroll
            for (int mi = 0; mi < MI; mi++)
#pragma unroll
                for (int ni = 0; ni < 4; ni++)
                    mma16816(acc[mi][ni], a[mi], b[ni]);
        }
    }

#pragma unroll
    for (int mi = 0; mi < MI; mi++) {
#pragma unroll
        for (int ni = 0; ni < 4; ni++) {
            int n0 = bn + wn + ni * 8 + 2 * t4;
            float2 b2 = *(const float2*)&bias[n0];
            float v0 = acc[mi][ni][0] + b2.x;
            float v1 = acc[mi][ni][1] + b2.y;
            float v2 = acc[mi][ni][2] + b2.x;
            float v3 = acc[mi][ni][3] + b2.y;
            int m0 = bm + wm + mi * 16 + g;
            size_t off0 = (size_t)m0 * N + n0;
            size_t off1 = (size_t)(m0 + 8) * N + n0;
            if (EPI == 1) {
                float2 r0 = *(const float2*)&res[off0];
                float2 r1 = *(const float2*)&res[off1];
                v0 += r0.x; v1 += r0.y; v2 += r1.x; v3 += r1.y;
                *(float2*)&C[off0] = make_float2(v0, v1);
                *(float2*)&C[off1] = make_float2(v2, v3);
            }
            if (EPI == 2) {
                v0 = gelu_tanh(v0); v1 = gelu_tanh(v1);
                v2 = gelu_tanh(v2); v3 = gelu_tanh(v3);
                *(uint32_t*)&Ch[off0] = pack2h(v0, v1);
                *(uint32_t*)&Ch[off1] = pack2h(v2, v3);
            }
            if (EPI == 3) {
                if (n0 < 2 * HIDDEN) {
                    int p = (n0 & 63) >> 1;
                    float c0 = cs[m0 * 32 + p],       s0 = sn[m0 * 32 + p];
                    float c1 = cs[(m0 + 8) * 32 + p], s1 = sn[(m0 + 8) * 32 + p];
                    float r0 = v0 * c0 - v1 * s0, i0 = v0 * s0 + v1 * c0;
                    float r1 = v2 * c1 - v3 * s1, i1 = v2 * s1 + v3 * c1;
                    if (n0 < HIDDEN) {
                        r0 *= 0.125f; i0 *= 0.125f;
                        r1 *= 0.125f; i1 *= 0.125f;
                    }
                    v0 = r0; v1 = i0; v2 = r1; v3 = i1;
                }
                *(uint32_t*)&Ch[off0] = pack2h(v0, v1);
                *(uint32_t*)&Ch[off1] = pack2h(v2, v3);
            }
        }
    }
}

#define SMEM_128 (NSTG * (128 + 128) * ROWB)
#define SMEM_64  (NSTG * (64 + 128) * ROWB)

// ---------------- Attention: HMMA flash, fp16 qkv, cp.async double-buffer ----
#define KROW 144

__global__ __launch_bounds__(128) void attn_mma(
    const __half* __restrict__ qkvh, const int* __restrict__ offs, int noffs,
    __half* __restrict__ o_out)
{
    __shared__ __align__(16) char sK[2][64 * KROW];
    __shared__ __align__(16) char sV[2][64 * KROW];
    __shared__ int segk[2][64];

    int head = blockIdx.x, qb = blockIdx.y;
    int tid  = threadIdx.x;
    int w = tid >> 5, lane = tid & 31;
    int t4 = lane & 3;
    int g = lane >> 2;

    uint32_t qh[4][4];
    int qr0 = qb * 64 + w * 16 + g;
    {
        const __half* q0 = qkvh + (size_t)qr0 * 3072 + head * 64;
#pragma unroll
        for (int kk = 0; kk < 4; kk++) {
            int c0 = kk * 16 + 2 * t4;
            qh[kk][0] = *(const uint32_t*)(q0 + c0);
            qh[kk][1] = *(const uint32_t*)(q0 + 8 * 3072 + c0);
            qh[kk][2] = *(const uint32_t*)(q0 + c0 + 8);
            qh[kk][3] = *(const uint32_t*)(q0 + 8 * 3072 + c0 + 8);
        }
    }
    int segq0 = 0, segq8 = 0;
    for (int t = 0; t < noffs; t++) {
        if (offs[t] <= qr0)     segq0++;
        if (offs[t] <= qr0 + 8) segq8++;
    }
    segq0--; segq8--;

    auto load_tile = [&](int kt) {
        int buf = kt & 1;
        int row = tid & 63;
        const __half* src = qkvh + (size_t)(kt * 64 + row) * 3072 +
                            ((tid < 64) ? 1024 : 2048) + head * 64;
        uint32_t dst = smem_u32((tid < 64) ? &sK[buf][row * KROW]
                                           : &sV[buf][row * KROW]);
#pragma unroll
        for (int i = 0; i < 8; i++) cp16(dst + i * 16, src + i * 8);
        cp_commit();
        if (tid < 64) {
            int kg = kt * 64 + tid;
            int c2 = 0;
            for (int t = 0; t < noffs; t++) if (offs[t] <= kg) c2++;
            segk[buf][tid] = c2 - 1;
        }
    };

    float o[8][4];
#pragma unroll
    for (int nt = 0; nt < 8; nt++)
#pragma unroll
        for (int q = 0; q < 4; q++) o[nt][q] = 0.f;
    float m0 = -1e30f, m8 = -1e30f, l0 = 0.f, l8 = 0.f;

    load_tile(0);

    for (int kt = 0; kt < SEQ / 64; kt++) {
        int buf = kt & 1;
        cp_wait0();
        __syncthreads();
        if (kt + 1 < SEQ / 64) load_tile(kt + 1);

        uint32_t aK = smem_u32(sK[buf]), aV = smem_u32(sV[buf]);

        float s[8][4];
#pragma unroll
        for (int nt = 0; nt < 8; nt++)
#pragma unroll
            for (int q = 0; q < 4; q++) s[nt][q] = 0.f;
#pragma unroll
        for (int kk = 0; kk < 4; kk++) {
#pragma unroll
            for (int nt = 0; nt < 8; nt++) {
                uint32_t off = (uint32_t)((nt * 8 + (lane & 7)) * KROW +
                                          (kk * 16 + ((lane >> 3) & 1) * 8) * 2);
                uint32_t bh[2];
                ldsm2(bh, aK + off);
                mma16816(s[nt], qh[kk], bh);
            }
        }
        float mt0 = -1e30f, mt8 = -1e30f;
#pragma unroll
        for (int nt = 0; nt < 8; nt++) {
            int sc0 = segk[buf][nt * 8 + 2 * t4];
            int sc1 = segk[buf][nt * 8 + 2 * t4 + 1];
            s[nt][0] += (segq0 == sc0) ? 1.f : 0.f;
            s[nt][1] += (segq0 == sc1) ? 1.f : 0.f;
            s[nt][2] += (segq8 == sc0) ? 1.f : 0.f;
            s[nt][3] += (segq8 == sc1) ? 1.f : 0.f;
            mt0 = fmaxf(mt0, fmaxf(s[nt][0], s[nt][1]));
            mt8 = fmaxf(mt8, fmaxf(s[nt][2], s[nt][3]));
        }
        mt0 = fmaxf(mt0, __shfl_xor_sync(0xffffffffu, mt0, 1));
        mt0 = fmaxf(mt0, __shfl_xor_sync(0xffffffffu, mt0, 2));
        mt8 = fmaxf(mt8, __shfl_xor_sync(0xffffffffu, mt8, 1));
        mt8 = fmaxf(mt8, __shfl_xor_sync(0xffffffffu, mt8, 2));
        float mn0 = fmaxf(m0, mt0), mn8 = fmaxf(m8, mt8);
        float corr0 = __expf(m0 - mn0), corr8 = __expf(m8 - mn8);
        m0 = mn0; m8 = mn8;
        float lp0 = 0.f, lp8 = 0.f;
#pragma unroll
        for (int nt = 0; nt < 8; nt++) {
            s[nt][0] = __expf(s[nt][0] - mn0);
            s[nt][1] = __expf(s[nt][1] - mn0);
            s[nt][2] = __expf(s[nt][2] - mn8);
            s[nt][3] = __expf(s[nt][3] - mn8);
            lp0 += s[nt][0] + s[nt][1];
            lp8 += s[nt][2] + s[nt][3];
        }
        lp0 += __shfl_xor_sync(0xffffffffu, lp0, 1);
        lp0 += __shfl_xor_sync(0xffffffffu, lp0, 2);
        lp8 += __shfl_xor_sync(0xffffffffu, lp8, 1);
        lp8 += __shfl_xor_sync(0xffffffffu, lp8, 2);
        l0 = l0 * corr0 + lp0;
        l8 = l8 * corr8 + lp8;
#pragma unroll
        for (int nt = 0; nt < 8; nt++) {
            o[nt][0] *= corr0; o[nt][1] *= corr0;
            o[nt][2] *= corr8; o[nt][3] *= corr8;
        }
#pragma unroll
        for (int kk = 0; kk < 4; kk++) {
            uint32_t pa[4];
            pa[0] = pack2h(s[2*kk][0],   s[2*kk][1]);
            pa[1] = pack2h(s[2*kk][2],   s[2*kk][3]);
            pa[2] = pack2h(s[2*kk+1][0], s[2*kk+1][1]);
            pa[3] = pack2h(s[2*kk+1][2], s[2*kk+1][3]);
#pragma unroll
            for (int nt = 0; nt < 8; nt++) {
                uint32_t off = (uint32_t)((kk * 16 + (lane & 15)) * KROW + nt * 16);
                uint32_t vh[2];
                ldsm2t(vh, aV + off);
                mma16816(o[nt], pa, vh);
            }
        }
        __syncthreads();
    }

    float inv0 = 1.f / l0, inv8 = 1.f / l8;
    size_t r0off = (size_t)qr0 * HIDDEN + head * 64;
    size_t r8off = r0off + 8 * HIDDEN;
#pragma unroll
    for (int nt = 0; nt < 8; nt++) {
        int col = nt * 8 + 2 * t4;
        *(uint32_t*)&o_out[r0off + col] = pack2h(o[nt][0] * inv0, o[nt][1] * inv0);
        *(uint32_t*)&o_out[r8off + col] = pack2h(o[nt][2] * inv8, o[nt][3] * inv8);
    }
}

// ---------------- launch ------------------------------------------------------
extern "C" void kernel_launch(void* const* d_in, const int* in_sizes, int n_in,
                              void* d_out, int out_size)
{
    const float* x        = (const float*)d_in[0];
    const float* rope_cos = (const float*)d_in[1];
    const float* rope_sin = (const float*)d_in[2];
    const float* norm0_w  = (const float*)d_in[3];
    const float* norm0_b  = (const float*)d_in[4];
    const float* norm1_w  = (const float*)d_in[5];
    const float* norm1_b  = (const float*)d_in[6];
    const float* wqkv_w   = (const float*)d_in[7];
    const float* wqkv_b   = (const float*)d_in[8];
    const float* wo_w     = (const float*)d_in[9];
    const float* wo_b     = (const float*)d_in[10];
    const float* up_w     = (const float*)d_in[11];
    const float* up_b     = (const float*)d_in[12];
    const float* down_w   = (const float*)d_in[13];
    const float* down_b   = (const float*)d_in[14];
    const int*   offs     = (const int*)d_in[15];
    int noffs = in_sizes[15];
    float* out = (float*)d_out;

    __half *h, *qkvh, *att, *h2, *u, *wqkv, *wo, *upw, *dnw;
    float *x1;
    cudaGetSymbolAddress((void**)&h,    g_h);
    cudaGetSymbolAddress((void**)&qkvh, g_qkvh);
    cudaGetSymbolAddress((void**)&att,  g_att);
    cudaGetSymbolAddress((void**)&x1,   g_x1);
    cudaGetSymbolAddress((void**)&h2,   g_h2);
    cudaGetSymbolAddress((void**)&u,    g_u);
    cudaGetSymbolAddress((void**)&wqkv, g_wqkv);
    cudaGetSymbolAddress((void**)&wo,   g_wo);
    cudaGetSymbolAddress((void**)&upw,  g_upw);
    cudaGetSymbolAddress((void**)&dnw,  g_dnw);

    cudaFuncSetAttribute((const void*)gemm_mma<3,128>, cudaFuncAttributeMaxDynamicSharedMemorySize, SMEM_128);
    cudaFuncSetAttribute((const void*)gemm_mma<2,128>, cudaFuncAttributeMaxDynamicSharedMemorySize, SMEM_128);
    cudaFuncSetAttribute((const void*)gemm_mma<1,64>,  cudaFuncAttributeMaxDynamicSharedMemorySize, SMEM_64);

    conv_kernel<<<(3*HIDDEN*HIDDEN/4 + 255)/256, 256>>>(wqkv_w, wqkv, 3*HIDDEN*HIDDEN/4);
    conv_kernel<<<(HIDDEN*HIDDEN/4 + 255)/256, 256>>>(wo_w, wo, HIDDEN*HIDDEN/4);
    conv_kernel<<<(MLP*HIDDEN/4 + 255)/256, 256>>>(up_w, upw, MLP*HIDDEN/4);
    conv_kernel<<<(HIDDEN*MLP/4 + 255)/256, 256>>>(down_w, dnw, HIDDEN*MLP/4);

    // 1. LN0 -> h (fp16)
    ln_kernel<<<SEQ, 256>>>(x, norm0_w, norm0_b, h);
    // 2. QKV GEMM + fused RoPE + q-scale -> qkvh (fp16)
    gemm_mma<3,128><<<dim3(3*HIDDEN/128, SEQ/128), 256, SMEM_128>>>(
        h, wqkv, wqkv_b, nullptr, rope_cos, rope_sin,
        nullptr, qkvh, SEQ, 3*HIDDEN, HIDDEN);
    // 3. attention -> att (fp16)
    attn_mma<<<dim3(NH, SEQ / 64), 128>>>(qkvh, offs, noffs, att);
    // 4. WO GEMM + residual -> x1 (fp32)   [BMT=64: 256 CTAs]
    gemm_mma<1,64><<<dim3(HIDDEN/128, SEQ/64), 256, SMEM_64>>>(
        att, wo, wo_b, x, nullptr, nullptr,
        x1, nullptr, SEQ, HIDDEN, HIDDEN);
    // 5. LN1 -> h2 (fp16)
    ln_kernel<<<SEQ, 256>>>(x1, norm1_w, norm1_b, h2);
    // 6. UP GEMM + GELU -> u (fp16)
    gemm_mma<2,128><<<dim3(MLP/128, SEQ/128), 256, SMEM_128>>>(
        h2, upw, up_b, nullptr, nullptr, nullptr,
        nullptr, u, SEQ, MLP, HIDDEN);
    // 7. DOWN GEMM + residual -> out (fp32)   [BMT=64: 256 CTAs]
    gemm_mma<1,64><<<dim3(HIDDEN/128, SEQ/64), 256, SMEM_64>>>(
        u, dnw, down_b, x1, nullptr, nullptr,
        out, nullptr, SEQ, HIDDEN, MLP);
}

// round 8
// speedup vs baseline: 13.0127x; 1.0668x over previous
#include <cuda_runtime.h>
#include <cuda_fp16.h>
#include <math.h>
#include <stdint.h>

#define SEQ    2048
#define HIDDEN 1024
#define MLP    4096
#define NH     16
#define HD     64

// ---------------- scratch (device globals: allocation-free) ----------------
__device__ __half g_h   [SEQ * HIDDEN];
__device__ __half g_qkvh[SEQ * 3 * HIDDEN];
__device__ __half g_att [SEQ * HIDDEN];
__device__ float  g_x1  [SEQ * HIDDEN];
__device__ __half g_h2  [SEQ * HIDDEN];
__device__ __half g_u   [SEQ * MLP];
__device__ __half g_wqkv[3 * HIDDEN * HIDDEN];
__device__ __half g_wo  [HIDDEN * HIDDEN];
__device__ __half g_upw [MLP * HIDDEN];
__device__ __half g_dnw [HIDDEN * MLP];

// ---------------- helpers ----------------------------------------------------
__device__ __forceinline__ uint32_t smem_u32(const void* p) {
    uint32_t a;
    asm("{ .reg .u64 t; cvta.to.shared.u64 t, %1; cvt.u32.u64 %0, t; }"
        : "=r"(a) : "l"(p));
    return a;
}
__device__ __forceinline__ void cp16(uint32_t saddr, const void* gptr) {
    asm volatile("cp.async.cg.shared.global [%0], [%1], 16;"
                 :: "r"(saddr), "l"(gptr));
}
__device__ __forceinline__ void cp_commit() {
    asm volatile("cp.async.commit_group;");
}
__device__ __forceinline__ void cp_wait1() {
    asm volatile("cp.async.wait_group 1;");
}
__device__ __forceinline__ void cp_wait0() {
    asm volatile("cp.async.wait_group 0;");
}
__device__ __forceinline__ void mma16816(float* c, const uint32_t* a, const uint32_t* b) {
    asm volatile(
        "mma.sync.aligned.m16n8k16.row.col.f32.f16.f16.f32 "
        "{%0,%1,%2,%3}, {%4,%5,%6,%7}, {%8,%9}, {%0,%1,%2,%3};"
        : "+f"(c[0]), "+f"(c[1]), "+f"(c[2]), "+f"(c[3])
        : "r"(a[0]), "r"(a[1]), "r"(a[2]), "r"(a[3]), "r"(b[0]), "r"(b[1]));
}
__device__ __forceinline__ void ldsm4(uint32_t* r, uint32_t a) {
    asm volatile("ldmatrix.sync.aligned.m8n8.x4.shared.b16 {%0,%1,%2,%3}, [%4];"
                 : "=r"(r[0]), "=r"(r[1]), "=r"(r[2]), "=r"(r[3]) : "r"(a));
}
__device__ __forceinline__ void ldsm2t(uint32_t* r, uint32_t a) {
    asm volatile("ldmatrix.sync.aligned.m8n8.x2.trans.shared.b16 {%0,%1}, [%2];"
                 : "=r"(r[0]), "=r"(r[1]) : "r"(a));
}
__device__ __forceinline__ uint32_t pack2h(float x, float y) {
    __half2 h = __floats2half2_rn(x, y);
    return *(uint32_t*)&h;
}
__device__ __forceinline__ float gelu_tanh(float v) {
    float c = 0.7978845608028654f * (v + 0.044715f * v * v * v);
    return 0.5f * v * (1.f + tanhf(c));
}

// ---------------- prep: all 4 weight conversions + LN0 in ONE launch ----------
#define CV1 786432              // wqkv float4 count
#define CV2 262144              // wo
#define CV3 1048576             // up
#define CV4 1048576             // down
#define CONV_BLOCKS ((CV1 + CV2 + CV3 + CV4) / 256)   // 12288

__global__ __launch_bounds__(256) void prep_kernel(
    const float* __restrict__ wqkv_w, const float* __restrict__ wo_w,
    const float* __restrict__ up_w,   const float* __restrict__ dn_w,
    __half* __restrict__ wqkv, __half* __restrict__ wo,
    __half* __restrict__ upw,  __half* __restrict__ dnw,
    const float* __restrict__ x, const float* __restrict__ n0w,
    const float* __restrict__ n0b, __half* __restrict__ h)
{
    int bid = blockIdx.x, tid = threadIdx.x;
    if (bid < CONV_BLOCKS) {
        int i = bid * 256 + tid;
        const float* src;
        __half* dst;
        if (i < CV1)                   { src = wqkv_w; dst = wqkv; }
        else if (i < CV1 + CV2)        { src = wo_w;  dst = wo;  i -= CV1; }
        else if (i < CV1 + CV2 + CV3)  { src = up_w;  dst = upw; i -= CV1 + CV2; }
        else                           { src = dn_w;  dst = dnw; i -= CV1 + CV2 + CV3; }
        float4 v = ((const float4*)src)[i];
        __half hh[4];
        hh[0] = __float2half_rn(v.x); hh[1] = __float2half_rn(v.y);
        hh[2] = __float2half_rn(v.z); hh[3] = __float2half_rn(v.w);
        *(uint2*)&dst[i * 4] = *(uint2*)hh;
        return;
    }
    // ---- LN0 ----
    int row = bid - CONV_BLOCKS;
    float4 v = *(const float4*)&x[row * HIDDEN + tid * 4];
    float s  = v.x + v.y + v.z + v.w;
    float ss = v.x*v.x + v.y*v.y + v.z*v.z + v.w*v.w;
#pragma unroll
    for (int o = 16; o > 0; o >>= 1) {
        s  += __shfl_xor_sync(0xffffffffu, s,  o);
        ss += __shfl_xor_sync(0xffffffffu, ss, o);
    }
    __shared__ float2 red[8];
    int wid = tid >> 5, lane = tid & 31;
    if (lane == 0) red[wid] = make_float2(s, ss);
    __syncthreads();
    if (tid < 32) {
        float2 t = (tid < 8) ? red[tid] : make_float2(0.f, 0.f);
        s = t.x; ss = t.y;
#pragma unroll
        for (int o = 4; o > 0; o >>= 1) {
            s  += __shfl_xor_sync(0xffffffffu, s,  o);
            ss += __shfl_xor_sync(0xffffffffu, ss, o);
        }
        if (lane == 0) red[0] = make_float2(s, ss);
    }
    __syncthreads();
    float mean = red[0].x * (1.f / HIDDEN);
    float var  = red[0].y * (1.f / HIDDEN) - mean * mean;
    float rstd = rsqrtf(var + 1e-5f);
    float4 w4 = *(const float4*)&n0w[tid * 4];
    float4 b4 = *(const float4*)&n0b[tid * 4];
    __half hh[4];
    hh[0] = __float2half_rn((v.x - mean) * rstd * w4.x + b4.x);
    hh[1] = __float2half_rn((v.y - mean) * rstd * w4.y + b4.y);
    hh[2] = __float2half_rn((v.z - mean) * rstd * w4.z + b4.z);
    hh[3] = __float2half_rn((v.w - mean) * rstd * w4.w + b4.w);
    *(uint2*)&h[row * HIDDEN + tid * 4] = *(uint2*)hh;
}

// ---------------- LayerNorm (fp32 in, fp16 out) -------------------------------
__global__ __launch_bounds__(256) void ln_kernel(
    const float* __restrict__ x, const float* __restrict__ w,
    const float* __restrict__ b, __half* __restrict__ y)
{
    int row = blockIdx.x;
    int tid = threadIdx.x;
    float4 v = *(const float4*)&x[row * HIDDEN + tid * 4];
    float s  = v.x + v.y + v.z + v.w;
    float ss = v.x*v.x + v.y*v.y + v.z*v.z + v.w*v.w;
#pragma unroll
    for (int o = 16; o > 0; o >>= 1) {
        s  += __shfl_xor_sync(0xffffffffu, s,  o);
        ss += __shfl_xor_sync(0xffffffffu, ss, o);
    }
    __shared__ float2 red[8];
    int wid = tid >> 5, lane = tid & 31;
    if (lane == 0) red[wid] = make_float2(s, ss);
    __syncthreads();
    if (tid < 32) {
        float2 t = (tid < 8) ? red[tid] : make_float2(0.f, 0.f);
        s = t.x; ss = t.y;
#pragma unroll
        for (int o = 4; o > 0; o >>= 1) {
            s  += __shfl_xor_sync(0xffffffffu, s,  o);
            ss += __shfl_xor_sync(0xffffffffu, ss, o);
        }
        if (lane == 0) red[0] = make_float2(s, ss);
    }
    __syncthreads();
    float mean = red[0].x * (1.f / HIDDEN);
    float var  = red[0].y * (1.f / HIDDEN) - mean * mean;
    float rstd = rsqrtf(var + 1e-5f);
    float4 w4 = *(const float4*)&w[tid * 4];
    float4 b4 = *(const float4*)&b[tid * 4];
    __half h[4];
    h[0] = __float2half_rn((v.x - mean) * rstd * w4.x + b4.x);
    h[1] = __float2half_rn((v.y - mean) * rstd * w4.y + b4.y);
    h[2] = __float2half_rn((v.z - mean) * rstd * w4.z + b4.z);
    h[3] = __float2half_rn((v.w - mean) * rstd * w4.w + b4.w);
    *(uint2*)&y[row * HIDDEN + tid * 4] = *(uint2*)h;
}

// ---------------- HMMA GEMM (NT): C = A @ B^T + bias -------------------------
#define BK 32
#define ROWB 80
#define NSTG 3

template <int EPI, int BMT>
__global__ __launch_bounds__(256) void gemm_mma(
    const __half* __restrict__ A, const __half* __restrict__ B,
    const float* __restrict__ bias, const float* __restrict__ res,
    const float* __restrict__ cs, const float* __restrict__ sn,
    float* __restrict__ C, __half* __restrict__ Ch, int M, int N, int K)
{
    constexpr int MI = BMT / 32;
    constexpr int STAGE = (BMT + 128) * ROWB;
    constexpr int NLOAD = (BMT + 128) * 4 / 256;

    extern __shared__ char smem[];
    uint32_t sb = smem_u32(smem);
    int tid = threadIdx.x, wid = tid >> 5, lane = tid & 31;
    int bm = blockIdx.y * BMT, bn = blockIdx.x * 128;
    int wm = (wid >> 2) * (MI * 16), wn = (wid & 3) * 32;
    int g = lane >> 2, t4 = lane & 3;

    float acc[MI][4][4];
#pragma unroll
    for (int i = 0; i < MI; i++)
#pragma unroll
        for (int j = 0; j < 4; j++)
#pragma unroll
            for (int q = 0; q < 4; q++) acc[i][j][q] = 0.f;

    int arow = (lane & 7) + ((lane >> 3) & 1) * 8;
    int acol = ((lane >> 4) & 1) * 8;
    int brow = ((lane >> 4) & 1) * 8 + (lane & 7);
    int bcol = ((lane >> 3) & 1) * 8;

    int T = K / BK;
    auto load_stage = [&](int t) {
        uint32_t sbase = sb + (t % NSTG) * STAGE;
        int k0 = t * BK;
#pragma unroll
        for (int i = 0; i < NLOAD; i++) {
            int idx = tid + i * 256;
            int r = idx >> 2, c8 = (idx & 3) * 8;
            const __half* gp = (r < BMT)
                ? A + (size_t)(bm + r) * K + k0 + c8
                : B + (size_t)(bn + (r - BMT)) * K + k0 + c8;
            cp16(sbase + r * ROWB + c8 * 2, gp);
        }
        cp_commit();
    };

    load_stage(0);
    load_stage(1);

    for (int t = 0; t < T; t++) {
        if (t + 1 < T) cp_wait1(); else cp_wait0();
        __syncthreads();
        if (t + 2 < T) load_stage(t + 2);

        uint32_t base = sb + (t % NSTG) * STAGE;
#pragma unroll
        for (int ks = 0; ks < 2; ks++) {
            uint32_t a[MI][4], b[4][2];
#pragma unroll
            for (int mi = 0; mi < MI; mi++)
                ldsm4(a[mi], base + (wm + mi * 16 + arow) * ROWB +
                             (ks * 16 + acol) * 2);
#pragma unroll
            for (int np = 0; np < 2; np++) {
                uint32_t tmp[4];
                ldsm4(tmp, base + BMT * ROWB + (wn + np * 16 + brow) * ROWB +
                           (ks * 16 + bcol) * 2);
                b[2*np][0] = tmp[0]; b[2*np][1] = tmp[1];
                b[2*np+1][0] = tmp[2]; b[2*np+1][1] = tmp[3];
            }
#pragma unroll
            for (int mi = 0; mi < MI; mi++)
#pragma unroll
                for (int ni = 0; ni < 4; ni++)
                    mma16816(acc[mi][ni], a[mi], b[ni]);
        }
    }

#pragma unroll
    for (int mi = 0; mi < MI; mi++) {
#pragma unroll
        for (int ni = 0; ni < 4; ni++) {
            int n0 = bn + wn + ni * 8 + 2 * t4;
            float2 b2 = *(const float2*)&bias[n0];
            float v0 = acc[mi][ni][0] + b2.x;
            float v1 = acc[mi][ni][1] + b2.y;
            float v2 = acc[mi][ni][2] + b2.x;
            float v3 = acc[mi][ni][3] + b2.y;
            int m0 = bm + wm + mi * 16 + g;
            size_t off0 = (size_t)m0 * N + n0;
            size_t off1 = (size_t)(m0 + 8) * N + n0;
            if (EPI == 1) {
                float2 r0 = *(const float2*)&res[off0];
                float2 r1 = *(const float2*)&res[off1];
                v0 += r0.x; v1 += r0.y; v2 += r1.x; v3 += r1.y;
                *(float2*)&C[off0] = make_float2(v0, v1);
                *(float2*)&C[off1] = make_float2(v2, v3);
            }
            if (EPI == 2) {
                v0 = gelu_tanh(v0); v1 = gelu_tanh(v1);
                v2 = gelu_tanh(v2); v3 = gelu_tanh(v3);
                *(uint32_t*)&Ch[off0] = pack2h(v0, v1);
                *(uint32_t*)&Ch[off1] = pack2h(v2, v3);
            }
            if (EPI == 3) {
                if (n0 < 2 * HIDDEN) {
                    int p = (n0 & 63) >> 1;
                    float c0 = cs[m0 * 32 + p],       s0 = sn[m0 * 32 + p];
                    float c1 = cs[(m0 + 8) * 32 + p], s1 = sn[(m0 + 8) * 32 + p];
                    float r0 = v0 * c0 - v1 * s0, i0 = v0 * s0 + v1 * c0;
                    float r1 = v2 * c1 - v3 * s1, i1 = v2 * s1 + v3 * c1;
                    if (n0 < HIDDEN) {
                        r0 *= 0.125f; i0 *= 0.125f;
                        r1 *= 0.125f; i1 *= 0.125f;
                    }
                    v0 = r0; v1 = i0; v2 = r1; v3 = i1;
                }
                *(uint32_t*)&Ch[off0] = pack2h(v0, v1);
                *(uint32_t*)&Ch[off1] = pack2h(v2, v3);
            }
        }
    }
}

#define SMEM_128 (NSTG * (128 + 128) * ROWB)
#define SMEM_64  (NSTG * (64 + 128) * ROWB)

// ---------------- Attention: HMMA flash, BQ=128 (8 warps), BKt=64 -------------
#define KROW 144

__global__ __launch_bounds__(256) void attn_mma(
    const __half* __restrict__ qkvh, const int* __restrict__ offs, int noffs,
    __half* __restrict__ o_out)
{
    __shared__ __align__(16) char sK[2][64 * KROW];
    __shared__ __align__(16) char sV[2][64 * KROW];
    __shared__ int segk[2][64];

    int head = blockIdx.x, qb = blockIdx.y;
    int tid  = threadIdx.x;
    int w = tid >> 5, lane = tid & 31;
    int t4 = lane & 3;
    int g = lane >> 2;
    int brow = ((lane >> 4) & 1) * 8 + (lane & 7);
    int bcol = ((lane >> 3) & 1) * 8;

    // ---- Q fragments (rope+scale pre-applied), one 16-row stripe per warp ----
    uint32_t qh[4][4];
    int qr0 = qb * 128 + w * 16 + g;
    {
        const __half* q0 = qkvh + (size_t)qr0 * 3072 + head * 64;
#pragma unroll
        for (int kk = 0; kk < 4; kk++) {
            int c0 = kk * 16 + 2 * t4;
            qh[kk][0] = *(const uint32_t*)(q0 + c0);
            qh[kk][1] = *(const uint32_t*)(q0 + 8 * 3072 + c0);
            qh[kk][2] = *(const uint32_t*)(q0 + c0 + 8);
            qh[kk][3] = *(const uint32_t*)(q0 + 8 * 3072 + c0 + 8);
        }
    }
    int segq0 = 0, segq8 = 0;
    for (int t = 0; t < noffs; t++) {
        if (offs[t] <= qr0)     segq0++;
        if (offs[t] <= qr0 + 8) segq8++;
    }
    segq0--; segq8--;

    // ---- K/V tile loader: 256 threads, 2 threads per 128B row ----
    auto load_tile = [&](int kt) {
        int buf = kt & 1;
        int row  = (tid >> 1) & 63;
        int half = tid & 1;
        int kv   = tid >> 7;   // 0 = K, 1 = V
        const __half* src = qkvh + (size_t)(kt * 64 + row) * 3072 +
                            (kv ? 2048 : 1024) + head * 64 + half * 32;
        uint32_t dst = smem_u32(kv ? &sV[buf][row * KROW + half * 64]
                                   : &sK[buf][row * KROW + half * 64]);
#pragma unroll
        for (int i = 0; i < 4; i++) cp16(dst + i * 16, src + i * 8);
        cp_commit();
        if (tid < 64) {
            int kg = kt * 64 + tid;
            int c2 = 0;
            for (int t = 0; t < noffs; t++) if (offs[t] <= kg) c2++;
            segk[buf][tid] = c2 - 1;
        }
    };

    float o[8][4];
#pragma unroll
    for (int nt = 0; nt < 8; nt++)
#pragma unroll
        for (int q = 0; q < 4; q++) o[nt][q] = 0.f;
    float m0 = -1e30f, m8 = -1e30f, l0 = 0.f, l8 = 0.f;

    load_tile(0);

    for (int kt = 0; kt < SEQ / 64; kt++) {
        int buf = kt & 1;
        cp_wait0();
        __syncthreads();
        if (kt + 1 < SEQ / 64) load_tile(kt + 1);

        uint32_t aK = smem_u32(sK[buf]), aV = smem_u32(sV[buf]);

        // ---- scores S = Q @ K^T (ldsm4 over nt pairs) ----
        float s[8][4];
#pragma unroll
        for (int nt = 0; nt < 8; nt++)
#pragma unroll
            for (int q = 0; q < 4; q++) s[nt][q] = 0.f;
#pragma unroll
        for (int kk = 0; kk < 4; kk++) {
#pragma unroll
            for (int ntp = 0; ntp < 4; ntp++) {
                uint32_t tmp[4];
                ldsm4(tmp, aK + (uint32_t)((ntp * 16 + brow) * KROW +
                                           (kk * 16 + bcol) * 2));
                uint32_t b0[2] = {tmp[0], tmp[1]};
                uint32_t b1[2] = {tmp[2], tmp[3]};
                mma16816(s[2*ntp],     qh[kk], b0);
                mma16816(s[2*ntp + 1], qh[kk], b1);
            }
        }
        // ---- +1.0 segment bias, online softmax ----
        float mt0 = -1e30f, mt8 = -1e30f;
#pragma unroll
        for (int nt = 0; nt < 8; nt++) {
            int sc0 = segk[buf][nt * 8 + 2 * t4];
            int sc1 = segk[buf][nt * 8 + 2 * t4 + 1];
            s[nt][0] += (segq0 == sc0) ? 1.f : 0.f;
            s[nt][1] += (segq0 == sc1) ? 1.f : 0.f;
            s[nt][2] += (segq8 == sc0) ? 1.f : 0.f;
            s[nt][3] += (segq8 == sc1) ? 1.f : 0.f;
            mt0 = fmaxf(mt0, fmaxf(s[nt][0], s[nt][1]));
            mt8 = fmaxf(mt8, fmaxf(s[nt][2], s[nt][3]));
        }
        mt0 = fmaxf(mt0, __shfl_xor_sync(0xffffffffu, mt0, 1));
        mt0 = fmaxf(mt0, __shfl_xor_sync(0xffffffffu, mt0, 2));
        mt8 = fmaxf(mt8, __shfl_xor_sync(0xffffffffu, mt8, 1));
        mt8 = fmaxf(mt8, __shfl_xor_sync(0xffffffffu, mt8, 2));
        float mn0 = fmaxf(m0, mt0), mn8 = fmaxf(m8, mt8);
        float corr0 = __expf(m0 - mn0), corr8 = __expf(m8 - mn8);
        m0 = mn0; m8 = mn8;
        float lp0 = 0.f, lp8 = 0.f;
#pragma unroll
        for (int nt = 0; nt < 8; nt++) {
            s[nt][0] = __expf(s[nt][0] - mn0);
            s[nt][1] = __expf(s[nt][1] - mn0);
            s[nt][2] = __expf(s[nt][2] - mn8);
            s[nt][3] = __expf(s[nt][3] - mn8);
            lp0 += s[nt][0] + s[nt][1];
            lp8 += s[nt][2] + s[nt][3];
        }
        lp0 += __shfl_xor_sync(0xffffffffu, lp0, 1);
        lp0 += __shfl_xor_sync(0xffffffffu, lp0, 2);
        lp8 += __shfl_xor_sync(0xffffffffu, lp8, 1);
        lp8 += __shfl_xor_sync(0xffffffffu, lp8, 2);
        l0 = l0 * corr0 + lp0;
        l8 = l8 * corr8 + lp8;
#pragma unroll
        for (int nt = 0; nt < 8; nt++) {
            o[nt][0] *= corr0; o[nt][1] *= corr0;
            o[nt][2] *= corr8; o[nt][3] *= corr8;
        }
        // ---- O += P @ V ----
#pragma unroll
        for (int kk = 0; kk < 4; kk++) {
            uint32_t pa[4];
            pa[0] = pack2h(s[2*kk][0],   s[2*kk][1]);
            pa[1] = pack2h(s[2*kk][2],   s[2*kk][3]);
            pa[2] = pack2h(s[2*kk+1][0], s[2*kk+1][1]);
            pa[3] = pack2h(s[2*kk+1][2], s[2*kk+1][3]);
#pragma unroll
            for (int nt = 0; nt < 8; nt++) {
                uint32_t off = (uint32_t)((kk * 16 + (lane & 15)) * KROW + nt * 16);
                uint32_t vh[2];
                ldsm2t(vh, aV + off);
                mma16816(o[nt], pa, vh);
            }
        }
        __syncthreads();
    }

    float inv0 = 1.f / l0, inv8 = 1.f / l8;
    size_t r0off = (size_t)qr0 * HIDDEN + head * 64;
    size_t r8off = r0off + 8 * HIDDEN;
#pragma unroll
    for (int nt = 0; nt < 8; nt++) {
        int col = nt * 8 + 2 * t4;
        *(uint32_t*)&o_out[r0off + col] = pack2h(o[nt][0] * inv0, o[nt][1] * inv0);
        *(uint32_t*)&o_out[r8off + col] = pack2h(o[nt][2] * inv8, o[nt][3] * inv8);
    }
}

// ---------------- launch ------------------------------------------------------
extern "C" void kernel_launch(void* const* d_in, const int* in_sizes, int n_in,
                              void* d_out, int out_size)
{
    const float* x        = (const float*)d_in[0];
    const float* rope_cos = (const float*)d_in[1];
    const float* rope_sin = (const float*)d_in[2];
    const float* norm0_w  = (const float*)d_in[3];
    const float* norm0_b  = (const float*)d_in[4];
    const float* norm1_w  = (const float*)d_in[5];
    const float* norm1_b  = (const float*)d_in[6];
    const float* wqkv_w   = (const float*)d_in[7];
    const float* wqkv_b   = (const float*)d_in[8];
    const float* wo_w     = (const float*)d_in[9];
    const float* wo_b     = (const float*)d_in[10];
    const float* up_w     = (const float*)d_in[11];
    const float* up_b     = (const float*)d_in[12];
    const float* down_w   = (const float*)d_in[13];
    const float* down_b   = (const float*)d_in[14];
    const int*   offs     = (const int*)d_in[15];
    int noffs = in_sizes[15];
    float* out = (float*)d_out;

    __half *h, *qkvh, *att, *h2, *u, *wqkv, *wo, *upw, *dnw;
    float *x1;
    cudaGetSymbolAddress((void**)&h,    g_h);
    cudaGetSymbolAddress((void**)&qkvh, g_qkvh);
    cudaGetSymbolAddress((void**)&att,  g_att);
    cudaGetSymbolAddress((void**)&x1,   g_x1);
    cudaGetSymbolAddress((void**)&h2,   g_h2);
    cudaGetSymbolAddress((void**)&u,    g_u);
    cudaGetSymbolAddress((void**)&wqkv, g_wqkv);
    cudaGetSymbolAddress((void**)&wo,   g_wo);
    cudaGetSymbolAddress((void**)&upw,  g_upw);
    cudaGetSymbolAddress((void**)&dnw,  g_dnw);

    cudaFuncSetAttribute((const void*)gemm_mma<3,128>, cudaFuncAttributeMaxDynamicSharedMemorySize, SMEM_128);
    cudaFuncSetAttribute((const void*)gemm_mma<2,128>, cudaFuncAttributeMaxDynamicSharedMemorySize, SMEM_128);
    cudaFuncSetAttribute((const void*)gemm_mma<1,64>,  cudaFuncAttributeMaxDynamicSharedMemorySize, SMEM_64);

    // 1. prep: all weight conversions + LN0 (single launch)
    prep_kernel<<<CONV_BLOCKS + SEQ, 256>>>(
        wqkv_w, wo_w, up_w, down_w, wqkv, wo, upw, dnw,
        x, norm0_w, norm0_b, h);
    // 2. QKV GEMM + fused RoPE + q-scale -> qkvh (fp16)
    gemm_mma<3,128><<<dim3(3*HIDDEN/128, SEQ/128), 256, SMEM_128>>>(
        h, wqkv, wqkv_b, nullptr, rope_cos, rope_sin,
        nullptr, qkvh, SEQ, 3*HIDDEN, HIDDEN);
    // 3. attention (BQ=128) -> att (fp16)
    attn_mma<<<dim3(NH, SEQ / 128), 256>>>(qkvh, offs, noffs, att);
    // 4. WO GEMM + residual -> x1 (fp32)
    gemm_mma<1,64><<<dim3(HIDDEN/128, SEQ/64), 256, SMEM_64>>>(
        att, wo, wo_b, x, nullptr, nullptr,
        x1, nullptr, SEQ, HIDDEN, HIDDEN);
    // 5. LN1 -> h2 (fp16)
    ln_kernel<<<SEQ, 256>>>(x1, norm1_w, norm1_b, h2);
    // 6. UP GEMM + GELU -> u (fp16)
    gemm_mma<2,128><<<dim3(MLP/128, SEQ/128), 256, SMEM_128>>>(
        h2, upw, up_b, nullptr, nullptr, nullptr,
        nullptr, u, SEQ, MLP, HIDDEN);
    // 7. DOWN GEMM + residual -> out (fp32)
    gemm_mma<1,64><<<dim3(HIDDEN/128, SEQ/64), 256, SMEM_64>>>(
        u, dnw, down_b, x1, nullptr, nullptr,
        out, nullptr, SEQ, HIDDEN, MLP);
}